// round 15
// baseline (speedup 1.0000x reference)
#include <cuda_runtime.h>
#include <cuda_bf16.h>
#include <cuda_fp16.h>
#include <cstdint>
#include <cstddef>

#define Bn 2
#define Nn 768
#define CS 1024
#define CZ 128
#define NH 16
#define HD 64
#define MROWS (Bn*Nn)     // 1536
#define NPAIR (Bn*Nn*Nn)  // 1179648
#define WSZ (CS*CS)

// ---------------- scratch (device globals; no allocations allowed) ----------------
__device__ __nv_bfloat16 d_Wh[5*WSZ];                        // weights, single fp16
__device__ __nv_bfloat16 d_inh[2*MROWS*CS], d_inl[2*MROWS*CS]; // s, k_in fp16 2-term
__device__ __nv_bfloat16 d_qh[MROWS*CS], d_ql[MROWS*CS];    // q fp16 2-term
__device__ __nv_bfloat16 d_kh[MROWS*CS];                    // k fp16
__device__ __nv_bfloat16 d_vh[MROWS*CS];                    // v fp16
__device__ __nv_bfloat16 d_goh[MROWS*CS], d_gol[MROWS*CS];  // go fp16 2-term
__device__ float d_g[MROWS*CS];
__device__ __half d_bias[Bn*NH*Nn*Nn];    // fp16 bias (37.7 MB)
__device__ float d_Gz[CZ*NH];
__device__ float d_Bh[NH];
__device__ float d_GzSum[NH];

// ================= helpers ====================
__device__ __forceinline__ void ldsm4(uint32_t* r, uint32_t a) {
    asm volatile("ldmatrix.sync.aligned.m8n8.x4.shared.b16 {%0,%1,%2,%3}, [%4];"
                 : "=r"(r[0]), "=r"(r[1]), "=r"(r[2]), "=r"(r[3]) : "r"(a));
}
__device__ __forceinline__ void ldsm4t(uint32_t* r, uint32_t a) {
    asm volatile("ldmatrix.sync.aligned.m8n8.x4.trans.shared.b16 {%0,%1,%2,%3}, [%4];"
                 : "=r"(r[0]), "=r"(r[1]), "=r"(r[2]), "=r"(r[3]) : "r"(a));
}
__device__ __forceinline__ void mma_bf16(float* c, const uint32_t* a, const uint32_t* b) {
    asm volatile("mma.sync.aligned.m16n8k16.row.col.f32.bf16.bf16.f32 "
                 "{%0,%1,%2,%3}, {%4,%5,%6,%7}, {%8,%9}, {%0,%1,%2,%3};"
                 : "+f"(c[0]), "+f"(c[1]), "+f"(c[2]), "+f"(c[3])
                 : "r"(a[0]), "r"(a[1]), "r"(a[2]), "r"(a[3]), "r"(b[0]), "r"(b[1]));
}
__device__ __forceinline__ void mma_f16(float* c, const uint32_t* a, const uint32_t* b) {
    asm volatile("mma.sync.aligned.m16n8k16.row.col.f32.f16.f16.f32 "
                 "{%0,%1,%2,%3}, {%4,%5,%6,%7}, {%8,%9}, {%0,%1,%2,%3};"
                 : "+f"(c[0]), "+f"(c[1]), "+f"(c[2]), "+f"(c[3])
                 : "r"(a[0]), "r"(a[1]), "r"(a[2]), "r"(a[3]), "r"(b[0]), "r"(b[1]));
}
__device__ __forceinline__ void split2(float x, float y, uint32_t& hi, uint32_t& lo) {
    __nv_bfloat162 h = __float22bfloat162_rn(make_float2(x, y));
    float2 hf = __bfloat1622float2(h);
    __nv_bfloat162 l = __float22bfloat162_rn(make_float2(x - hf.x, y - hf.y));
    hi = *(uint32_t*)&h;
    lo = *(uint32_t*)&l;
}
__device__ __forceinline__ void split2h(float x, float y, uint32_t& hi, uint32_t& lo) {
    __half2 h = __floats2half2_rn(x, y);
    float2 hf = __half22float2(h);
    __half2 l = __floats2half2_rn(x - hf.x, y - hf.y);
    hi = *(uint32_t*)&h;
    lo = *(uint32_t*)&l;
}
#define CPA(dst, src) asm volatile("cp.async.cg.shared.global [%0], [%1], 16;" :: "r"(dst), "l"(src))
#define CPCOMMIT()    asm volatile("cp.async.commit_group;")
#define CPWAIT1()     asm volatile("cp.async.wait_group 1;")

// ---------------- pre-split converters ----------------
__global__ void __launch_bounds__(256) wconv_kernel(
    const float* __restrict__ W0, const float* __restrict__ W1,
    const float* __restrict__ W2, const float* __restrict__ W3,
    const float* __restrict__ W4)
{
    int which = blockIdx.y;
    const float* src = which == 0 ? W0 : which == 1 ? W1 : which == 2 ? W2 :
                       which == 3 ? W3 : W4;
    size_t idx = ((size_t)blockIdx.x * 256 + threadIdx.x) * 4;
    float4 v = *(const float4*)(src + idx);
    __half2 a = __floats2half2_rn(v.x, v.y);
    __half2 b = __floats2half2_rn(v.z, v.w);
    size_t o = (size_t)which * WSZ + idx;
    *(uint2*)((char*)d_Wh + o*2) = make_uint2(*(uint32_t*)&a, *(uint32_t*)&b);
}
__global__ void __launch_bounds__(256) aconv_kernel(
    const float* __restrict__ A0, const float* __restrict__ A1)
{
    int which = blockIdx.y;
    const float* src = which == 0 ? A0 : A1;
    size_t idx = ((size_t)blockIdx.x * 256 + threadIdx.x) * 4;
    float4 v = *(const float4*)(src + idx);
    uint32_t h0, l0, h1, l1;
    split2h(v.x, v.y, h0, l0);
    split2h(v.z, v.w, h1, l1);
    size_t o = (size_t)which * MROWS * CS + idx;
    *(uint2*)((char*)d_inh + o*2) = make_uint2(h0, h1);
    *(uint2*)((char*)d_inl + o*2) = make_uint2(l0, l1);
}

// ================= GEMM body: fp16 2-term A (1-term for sigmoid), fp16 B, 2-stage =====
#define ASTRIDE 40
#define BSTRIDE 72
#define AHI_OFF 0
#define ALO_OFF 10240
#define BHI_OFF 20480
#define BUFBYTES 25088
#define GEMM_SMEM (2*BUFBYTES)   // 50176

__device__ __forceinline__ void gemm_body(
    char* sm_raw, int m0, int n0,
    const __nv_bfloat16* __restrict__ Ah, const __nv_bfloat16* __restrict__ Al,
    const __nv_bfloat16* __restrict__ Bh,
    const float* __restrict__ bq, int mode,
    float* __restrict__ Cf, __nv_bfloat16* __restrict__ Ch, __nv_bfloat16* __restrict__ Cl)
{
    uint32_t sbase = (uint32_t)__cvta_generic_to_shared(sm_raw);
    const bool twoterm = (mode != 3);

    int tid = threadIdx.x;
    int wid = tid >> 5, lane = tid & 31;
    int warpM = wid >> 1, warpN = wid & 1;

    float acc[2][4][4];
    #pragma unroll
    for (int mt = 0; mt < 2; mt++)
        #pragma unroll
        for (int nt = 0; nt < 4; nt++)
            #pragma unroll
            for (int i = 0; i < 4; i++) acc[mt][nt][i] = 0.f;

    int matr = lane >> 3, rr = lane & 7;
    int aRowBase = warpM * 32 + (matr & 1) * 8 + rr;
    int aColBase = (matr >> 1) * 8;
    int bRowBase = (matr & 1) * 8 + rr;
    int bColBase = warpN * 32 + (matr >> 1) * 8;

    int arow = tid >> 2, aq = tid & 3;
    int brow = tid >> 3, bqc = tid & 7;

    auto issue = [&](int c, int buf) {
        uint32_t st = sbase + buf * BUFBYTES;
        #pragma unroll
        for (int r = 0; r < 2; r++) {
            int row = arow + r * 64;
            const __nv_bfloat16* sh = Ah + (size_t)(m0 + row) * CS + c * 32 + aq * 8;
            uint32_t d = st + row * 80 + aq * 16;
            CPA(d + AHI_OFF, sh);
            if (twoterm) {
                const __nv_bfloat16* sl = Al + (size_t)(m0 + row) * CS + c * 32 + aq * 8;
                CPA(d + ALO_OFF, sl);
            }
        }
        {
            const __nv_bfloat16* sh = Bh + (size_t)(c * 32 + brow) * CS + n0 + bqc * 8;
            CPA(st + BHI_OFF + brow * 144 + bqc * 16, sh);
        }
    };

    issue(0, 0); CPCOMMIT();

    const int CHUNKS = 32;
    for (int c = 0; c < CHUNKS; c++) {
        __syncthreads();                        // prior compute done with buf (c+1)&1
        if (c + 1 < CHUNKS) issue(c + 1, (c + 1) & 1);
        CPCOMMIT();
        CPWAIT1();                              // all but newest group done => chunk c ready
        __syncthreads();

        uint32_t off = sbase + (c & 1) * BUFBYTES;
        #pragma unroll
        for (int ks = 0; ks < 32; ks += 16) {
            uint32_t Ahf[2][4], Alf[2][4], Bhf[2][4];
            #pragma unroll
            for (int mt = 0; mt < 2; mt++)
                ldsm4(Ahf[mt], off + AHI_OFF +
                      (((aRowBase + mt * 16) * ASTRIDE) + aColBase + ks) * 2);
            #pragma unroll
            for (int ntp = 0; ntp < 2; ntp++)
                ldsm4t(Bhf[ntp], off + BHI_OFF +
                       (((bRowBase + ks) * BSTRIDE) + bColBase + ntp * 16) * 2);
            #pragma unroll
            for (int mt = 0; mt < 2; mt++)
                #pragma unroll
                for (int nt = 0; nt < 4; nt++)
                    mma_f16(acc[mt][nt], Ahf[mt], &Bhf[nt >> 1][(nt & 1) * 2]);
            if (twoterm) {
                #pragma unroll
                for (int mt = 0; mt < 2; mt++)
                    ldsm4(Alf[mt], off + ALO_OFF +
                          (((aRowBase + mt * 16) * ASTRIDE) + aColBase + ks) * 2);
                #pragma unroll
                for (int mt = 0; mt < 2; mt++)
                    #pragma unroll
                    for (int nt = 0; nt < 4; nt++)
                        mma_f16(acc[mt][nt], Alf[mt], &Bhf[nt >> 1][(nt & 1) * 2]);
            }
        }
    }

    int grp = lane >> 2, tL = lane & 3;
    #pragma unroll
    for (int mt = 0; mt < 2; mt++) {
        #pragma unroll
        for (int nt = 0; nt < 4; nt++) {
            int row = m0 + warpM * 32 + mt * 16 + grp;
            int col = n0 + warpN * 32 + nt * 8 + tL * 2;
            float v0 = acc[mt][nt][0], v1 = acc[mt][nt][1];
            float v2 = acc[mt][nt][2], v3 = acc[mt][nt][3];
            if (mode == 0) {
                float b0 = bq[col], b1 = bq[col + 1];
                v0 = (v0 + b0) * 0.125f; v1 = (v1 + b1) * 0.125f;
                v2 = (v2 + b0) * 0.125f; v3 = (v3 + b1) * 0.125f;
                uint32_t h0, l0, h1, l1;
                split2h(v0, v1, h0, l0);
                split2h(v2, v3, h1, l1);
                *(uint32_t*)((char*)Ch + ((size_t)row * CS + col) * 2)       = h0;
                *(uint32_t*)((char*)Cl + ((size_t)row * CS + col) * 2)       = l0;
                *(uint32_t*)((char*)Ch + ((size_t)(row + 8) * CS + col) * 2) = h1;
                *(uint32_t*)((char*)Cl + ((size_t)(row + 8) * CS + col) * 2) = l1;
            } else if (mode == 1 || mode == 2) {
                __half2 a = __floats2half2_rn(v0, v1);
                __half2 b2 = __floats2half2_rn(v2, v3);
                *(uint32_t*)((char*)Ch + ((size_t)row * CS + col) * 2)       = *(uint32_t*)&a;
                *(uint32_t*)((char*)Ch + ((size_t)(row + 8) * CS + col) * 2) = *(uint32_t*)&b2;
            } else if (mode == 3) {
                v0 = 1.f/(1.f + __expf(-v0)); v1 = 1.f/(1.f + __expf(-v1));
                v2 = 1.f/(1.f + __expf(-v2)); v3 = 1.f/(1.f + __expf(-v3));
                *(float2*)(Cf + (size_t)row * CS + col)       = make_float2(v0, v1);
                *(float2*)(Cf + (size_t)(row + 8) * CS + col) = make_float2(v2, v3);
            } else {
                *(float2*)(Cf + (size_t)row * CS + col)       = make_float2(v0, v1);
                *(float2*)(Cf + (size_t)(row + 8) * CS + col) = make_float2(v2, v3);
            }
        }
    }
}

// ================ bias body (direct gmem fragments, fp16 out) ================
#define BM_GH 0
#define BM_GL 6144
#define BM_SG 12288     // stage float[128*17] = 8704 -> total 20992 <= GEMM_SMEM

__device__ __forceinline__ void bias_body(char* smraw, int tile, const float* __restrict__ z)
{
    uint32_t sb = (uint32_t)__cvta_generic_to_shared(smraw);
    int tid = threadIdx.x, lane = tid & 31, wid = tid >> 5;
    int grp = lane >> 2, tL = lane & 3;
    int t8 = lane >> 3, r8 = lane & 7;

    for (int t = tid; t < CZ*NH; t += 256) {
        int c = t >> 4, hh = t & 15;
        int cb = c & 15, tq = cb >> 2, j = cb & 3;
        int lr = (j < 2) ? (2*tq + j) : (8 + 2*tq + (j - 2));
        int row = (c & 0x70) | lr;
        float w = d_Gz[t];
        __nv_bfloat16 hi = __float2bfloat16(w);
        __nv_bfloat16 lo = __float2bfloat16(w - __bfloat162float(hi));
        ((__nv_bfloat16*)(smraw + BM_GH))[row*24 + hh] = hi;
        ((__nv_bfloat16*)(smraw + BM_GL))[row*24 + hh] = lo;
    }
    __syncthreads();

    const float* z0 = z + (size_t)(tile*128 + wid*16 + grp)*CZ;
    const float* z1 = z0 + 8*CZ;

    int gRow = (t8 & 1)*8 + r8;
    int gCol = (t8 >> 1)*8;

    float acc0[4] = {0.f,0.f,0.f,0.f}, acc1[4] = {0.f,0.f,0.f,0.f};
    float s1_0 = 0.f, s2_0 = 0.f, s1_1 = 0.f, s2_1 = 0.f;

    #pragma unroll
    for (int kc = 0; kc < 8; kc++) {
        float4 f = *(const float4*)(z0 + kc*16 + tL*4);
        float4 g = *(const float4*)(z1 + kc*16 + tL*4);

        s1_0 += (f.x + f.y) + (f.z + f.w);
        s2_0 = fmaf(f.x,f.x, fmaf(f.y,f.y, fmaf(f.z,f.z, fmaf(f.w,f.w, s2_0))));
        s1_1 += (g.x + g.y) + (g.z + g.w);
        s2_1 = fmaf(g.x,g.x, fmaf(g.y,g.y, fmaf(g.z,g.z, fmaf(g.w,g.w, s2_1))));

        uint32_t Ahf[4], Alf[4];
        split2(f.x, f.y, Ahf[0], Alf[0]);
        split2(g.x, g.y, Ahf[1], Alf[1]);
        split2(f.z, f.w, Ahf[2], Alf[2]);
        split2(g.z, g.w, Ahf[3], Alf[3]);

        uint32_t Gh[4], Gl[4];
        uint32_t goff = (uint32_t)(((gRow + kc*16)*24 + gCol) * 2);
        ldsm4t(Gh, sb + BM_GH + goff);
        ldsm4t(Gl, sb + BM_GL + goff);

        mma_bf16(acc0, Ahf, &Gh[0]); mma_bf16(acc1, Ahf, &Gh[2]);
        mma_bf16(acc0, Alf, &Gh[0]); mma_bf16(acc1, Alf, &Gh[2]);
        mma_bf16(acc0, Ahf, &Gl[0]); mma_bf16(acc1, Ahf, &Gl[2]);
    }

    s1_0 += __shfl_xor_sync(0xFFFFFFFFu, s1_0, 1);
    s1_0 += __shfl_xor_sync(0xFFFFFFFFu, s1_0, 2);
    s2_0 += __shfl_xor_sync(0xFFFFFFFFu, s2_0, 1);
    s2_0 += __shfl_xor_sync(0xFFFFFFFFu, s2_0, 2);
    s1_1 += __shfl_xor_sync(0xFFFFFFFFu, s1_1, 1);
    s1_1 += __shfl_xor_sync(0xFFFFFFFFu, s1_1, 2);
    s2_1 += __shfl_xor_sync(0xFFFFFFFFu, s2_1, 1);
    s2_1 += __shfl_xor_sync(0xFFFFFFFFu, s2_1, 2);
    float mu0 = s1_0 * (1.f/128.f);
    float rstd0 = rsqrtf(s2_0 * (1.f/128.f) - mu0*mu0 + 1e-5f);
    float mu1 = s1_1 * (1.f/128.f);
    float rstd1 = rsqrtf(s2_1 * (1.f/128.f) - mu1*mu1 + 1e-5f);

    {
        int r0 = wid*16 + grp, r1 = r0 + 8;
        float* stage = (float*)(smraw + BM_SG);
        #pragma unroll
        for (int n = 0; n < 2; n++) {
            float* a = n ? acc1 : acc0;
            int h = n*8 + tL*2;
            float gs0 = d_GzSum[h], gs1 = d_GzSum[h+1];
            float bh0 = d_Bh[h],    bh1 = d_Bh[h+1];
            stage[r0*17 + h]     = rstd0*(a[0] - mu0*gs0) + bh0;
            stage[r0*17 + h + 1] = rstd0*(a[1] - mu0*gs1) + bh1;
            stage[r1*17 + h]     = rstd1*(a[2] - mu1*gs0) + bh0;
            stage[r1*17 + h + 1] = rstd1*(a[3] - mu1*gs1) + bh1;
        }
    }
    __syncthreads();

    {
        int p0  = tile * 128;
        int b   = p0 / (Nn*Nn);
        int rem = p0 % (Nn*Nn);
        int ii  = rem / Nn;
        int j0  = rem % Nn;
        float* stage = (float*)(smraw + BM_SG);
        #pragma unroll
        for (int t = tid; t < 128*8; t += 256) {
            int h = t >> 6, rr2 = (t & 63) * 2;
            __half2 val = __floats2half2_rn(stage[rr2*17 + h], stage[(rr2+1)*17 + h]);
            *(__half2*)(d_bias + ((size_t)(b*NH + h)*Nn + ii)*Nn + j0 + rr2) = val;
        }
    }
}

// ======= fused mid kernel: 9984 blocks = 9216 bias tiles + 768 proj tiles (every 13th) =======
__global__ void __launch_bounds__(256) fused_mid(const float* __restrict__ bq,
                                                 const float* __restrict__ z)
{
    extern __shared__ char smem[];
    int b = blockIdx.x;
    int q13 = b / 13;
    if (b - q13 * 13 == 0) {
        // proj tile
        int which = q13 / 192, r = q13 % 192;
        int n0 = (r & 15) * 64, m0 = (r >> 4) * 128;
        const __nv_bfloat16* Ah = (which == 0 || which == 3) ? d_inh : d_inh + MROWS*CS;
        const __nv_bfloat16* Al = (which == 0 || which == 3) ? d_inl : d_inl + MROWS*CS;
        const __nv_bfloat16* Bh = d_Wh + (size_t)which * WSZ;
        __nv_bfloat16* Ch = which == 0 ? d_qh : which == 1 ? d_kh : which == 2 ? d_vh : nullptr;
        __nv_bfloat16* Cl = which == 0 ? d_ql : nullptr;
        gemm_body(smem, m0, n0, Ah, Al, Bh, bq, which, d_g, Ch, Cl);
    } else {
        bias_body(smem, b - q13 - 1, z);
    }
}

__global__ void __launch_bounds__(256) final_gemm(float* __restrict__ out)
{
    extern __shared__ char smem[];
    gemm_body(smem, blockIdx.y * 128, blockIdx.x * 64,
              d_goh, d_gol, d_Wh + 4*(size_t)WSZ, nullptr, 4, out, nullptr, nullptr);
}

// ---------------- fold LN affine into z-projection ----------------
__global__ void prep_kernel(const float* __restrict__ ln_g,
                            const float* __restrict__ ln_b,
                            const float* __restrict__ Wz)
{
    __shared__ float sB[CZ*NH];
    __shared__ float sG[CZ*NH];
    int c = threadIdx.x;
    float g = ln_g[c], bb = ln_b[c];
    #pragma unroll
    for (int h = 0; h < NH; h++) {
        float w = Wz[c*NH + h];
        float gz = g*w;
        d_Gz[c*NH + h] = gz;
        sG[c*NH + h] = gz;
        sB[c*NH + h] = bb*w;
    }
    __syncthreads();
    if (c < NH) {
        float sb = 0.f, sg = 0.f;
        for (int cc = 0; cc < CZ; cc++) { sb += sB[cc*NH + c]; sg += sG[cc*NH + c]; }
        d_Bh[c] = sb;
        d_GzSum[c] = sg;
    }
}

// ========== flash attention: 128 threads, 32-row i-tile ==========
#define AT_STRIDE 72
#define AQ_H 0
#define AQ_L 4608
#define KV0 9216
#define KVSTAGE 18432
#define OSM_OFF 0
#define OSM_STRIDE 68
#define STAT_OFF 17408
#define ATT_SMEM 46080

__global__ void __launch_bounds__(128, 4) attn_mma(const float* __restrict__ mask)
{
    extern __shared__ char smraw[];
    uint32_t sb = (uint32_t)__cvta_generic_to_shared(smraw);
    int tid = threadIdx.x, lane = tid & 31, wid = tid >> 5;
    int warpM = wid >> 1, warpN = wid & 1;
    int b = blockIdx.z, h = blockIdx.y, i0 = blockIdx.x * 32;
    int grp = lane >> 2, tL = lane & 3;
    int t8 = lane >> 3, r8 = lane & 7;

    {
        #pragma unroll
        for (int i = 0; i < 4; i++) {
            int g = tid + i*128;
            int mtx = g >> 8, r = (g >> 3) & 31, q = g & 7;
            const __nv_bfloat16* src = (mtx ? d_ql : d_qh) +
                (size_t)(b*Nn + i0 + r)*CS + h*HD + q*8;
            CPA(sb + mtx*4608 + r*144 + q*16, src);
        }
        #pragma unroll
        for (int i = 0; i < 8; i++) {
            int g = tid + i*128;
            int mtx = g >> 9, r = (g >> 3) & 63, q = g & 7;
            const __nv_bfloat16* src = (mtx ? d_vh : d_kh) +
                (size_t)(b*Nn + r)*CS + h*HD + q*8;
            CPA(sb + KV0 + mtx*9216 + r*144 + q*16, src);
        }
        CPCOMMIT();
    }

    float Oa[8][4];
    #pragma unroll
    for (int t = 0; t < 8; t++) { Oa[t][0]=0.f; Oa[t][1]=0.f; Oa[t][2]=0.f; Oa[t][3]=0.f; }
    float mrow0 = -1e30f, mrow1 = -1e30f, lsum0 = 0.f, lsum1 = 0.f;

    const float* maskp = mask + b*Nn;
    const __half* biasbase = d_bias + ((size_t)(b*NH + h)*Nn + (i0 + warpM*16 + grp))*Nn;

    int aRow  = warpM*16 + (t8 & 1)*8 + r8;
    int aCol  = (t8 >> 1)*8;
    int kRowB = warpN*32 + (t8 >> 1)*8 + r8;
    int kColB = (t8 & 1)*8;
    int vRowB = (t8 & 1)*8 + r8;
    int vColB = (t8 >> 1)*8;

    #pragma unroll 1
    for (int jt = 0; jt < 12; jt++) {
        int j0c = jt * 64;
        __syncthreads();
        if (jt + 1 < 12) {
            int st1 = (jt + 1) & 1;
            #pragma unroll
            for (int i = 0; i < 8; i++) {
                int g = tid + i*128;
                int mtx = g >> 9, r = (g >> 3) & 63, q = g & 7;
                const __nv_bfloat16* src = (mtx ? d_vh : d_kh) +
                    (size_t)(b*Nn + j0c + 64 + r)*CS + h*HD + q*8;
                CPA(sb + KV0 + st1*KVSTAGE + mtx*9216 + r*144 + q*16, src);
            }
        }
        CPCOMMIT();
        CPWAIT1();
        __syncthreads();

        uint32_t ks = sb + KV0 + (jt & 1)*KVSTAGE;

        float S[4][4];
        #pragma unroll
        for (int nt = 0; nt < 4; nt++) { S[nt][0]=0.f; S[nt][1]=0.f; S[nt][2]=0.f; S[nt][3]=0.f; }
        #pragma unroll
        for (int kk = 0; kk < 4; kk++) {
            uint32_t qh_[4], ql_[4], khf[2][4];
            uint32_t aoff = (uint32_t)((aRow*AT_STRIDE + kk*16 + aCol) * 2);
            ldsm4(qh_, sb + AQ_H + aoff);
            ldsm4(ql_, sb + AQ_L + aoff);
            uint32_t koff0 = (uint32_t)((kRowB*AT_STRIDE + kk*16 + kColB) * 2);
            uint32_t koff1 = (uint32_t)(((kRowB+16)*AT_STRIDE + kk*16 + kColB) * 2);
            ldsm4(khf[0], ks + koff0);
            ldsm4(khf[1], ks + koff1);
            #pragma unroll
            for (int nt = 0; nt < 4; nt++)
                mma_f16(S[nt], qh_, &khf[nt >> 1][(nt & 1)*2]);
            #pragma unroll
            for (int nt = 0; nt < 4; nt++)
                mma_f16(S[nt], ql_, &khf[nt >> 1][(nt & 1)*2]);
        }

        #pragma unroll
        for (int nt = 0; nt < 4; nt++) {
            int jc = j0c + warpN*32 + nt*8 + tL*2;
            float2 b0 = __half22float2(*(const __half2*)(biasbase + jc));
            float2 b1 = __half22float2(*(const __half2*)(biasbase + (size_t)8*Nn + jc));
            float2 mv = *(const float2*)(maskp + jc);
            float mk0 = (1.f - mv.x) * (-1000000.0f);
            float mk1 = (1.f - mv.y) * (-1000000.0f);
            S[nt][0] += b0.x + mk0; S[nt][1] += b0.y + mk1;
            S[nt][2] += b1.x + mk0; S[nt][3] += b1.y + mk1;
        }

        float cm0 = fmaxf(fmaxf(S[0][0], S[0][1]), fmaxf(S[1][0], S[1][1]));
        cm0 = fmaxf(cm0, fmaxf(fmaxf(S[2][0], S[2][1]), fmaxf(S[3][0], S[3][1])));
        float cm1 = fmaxf(fmaxf(S[0][2], S[0][3]), fmaxf(S[1][2], S[1][3]));
        cm1 = fmaxf(cm1, fmaxf(fmaxf(S[2][2], S[2][3]), fmaxf(S[3][2], S[3][3])));
        cm0 = fmaxf(cm0, __shfl_xor_sync(0xFFFFFFFFu, cm0, 1));
        cm0 = fmaxf(cm0, __shfl_xor_sync(0xFFFFFFFFu, cm0, 2));
        cm1 = fmaxf(cm1, __shfl_xor_sync(0xFFFFFFFFu, cm1, 1));
        cm1 = fmaxf(cm1, __shfl_xor_sync(0xFFFFFFFFu, cm1, 2));
        float mn0 = fmaxf(mrow0, cm0), mn1 = fmaxf(mrow1, cm1);
        float sc0 = __expf(mrow0 - mn0), sc1 = __expf(mrow1 - mn1);
        mrow0 = mn0; mrow1 = mn1;
        float rs0 = 0.f, rs1 = 0.f;
        #pragma unroll
        for (int nt = 0; nt < 4; nt++) {
            S[nt][0] = __expf(S[nt][0] - mn0);
            S[nt][1] = __expf(S[nt][1] - mn0);
            S[nt][2] = __expf(S[nt][2] - mn1);
            S[nt][3] = __expf(S[nt][3] - mn1);
            rs0 += S[nt][0] + S[nt][1];
            rs1 += S[nt][2] + S[nt][3];
        }
        rs0 += __shfl_xor_sync(0xFFFFFFFFu, rs0, 1);
        rs0 += __shfl_xor_sync(0xFFFFFFFFu, rs0, 2);
        rs1 += __shfl_xor_sync(0xFFFFFFFFu, rs1, 1);
        rs1 += __shfl_xor_sync(0xFFFFFFFFu, rs1, 2);
        lsum0 = lsum0*sc0 + rs0;
        lsum1 = lsum1*sc1 + rs1;
        #pragma unroll
        for (int t = 0; t < 8; t++) {
            Oa[t][0] *= sc0; Oa[t][1] *= sc0;
            Oa[t][2] *= sc1; Oa[t][3] *= sc1;
        }

        uint32_t Ph[2][4], Pl[2][4];
        #pragma unroll
        for (int kf = 0; kf < 2; kf++) {
            split2h(S[2*kf][0],   S[2*kf][1],   Ph[kf][0], Pl[kf][0]);
            split2h(S[2*kf][2],   S[2*kf][3],   Ph[kf][1], Pl[kf][1]);
            split2h(S[2*kf+1][0], S[2*kf+1][1], Ph[kf][2], Pl[kf][2]);
            split2h(S[2*kf+1][2], S[2*kf+1][3], Ph[kf][3], Pl[kf][3]);
        }

        #pragma unroll
        for (int kf = 0; kf < 2; kf++) {
            int kb = warpN*32 + kf*16;
            #pragma unroll
            for (int ntp = 0; ntp < 4; ntp++) {
                uint32_t vhf[4];
                uint32_t voff = (uint32_t)(((kb + vRowB)*AT_STRIDE + ntp*16 + vColB) * 2);
                ldsm4t(vhf, ks + 9216 + voff);
                mma_f16(Oa[ntp*2],   Ph[kf], &vhf[0]);
                mma_f16(Oa[ntp*2+1], Ph[kf], &vhf[2]);
                mma_f16(Oa[ntp*2],   Pl[kf], &vhf[0]);
                mma_f16(Oa[ntp*2+1], Pl[kf], &vhf[2]);
            }
        }
    }

    __syncthreads();
    float* Osm  = (float*)(smraw + OSM_OFF);
    float* stat = (float*)(smraw + STAT_OFF);
    #pragma unroll
    for (int t = 0; t < 8; t++) {
        int dcol = t*8 + tL*2;
        Osm[(wid*16 + grp)*OSM_STRIDE + dcol]       = Oa[t][0];
        Osm[(wid*16 + grp)*OSM_STRIDE + dcol + 1]   = Oa[t][1];
        Osm[(wid*16 + grp+8)*OSM_STRIDE + dcol]     = Oa[t][2];
        Osm[(wid*16 + grp+8)*OSM_STRIDE + dcol + 1] = Oa[t][3];
    }
    if (tL == 0) {
        stat[wid*32 + grp*2]       = mrow0;
        stat[wid*32 + grp*2 + 1]   = lsum0;
        stat[wid*32 + (grp+8)*2]     = mrow1;
        stat[wid*32 + (grp+8)*2 + 1] = lsum1;
    }
    __syncthreads();

    for (int t = tid; t < 32*32; t += 128) {
        int row = t >> 5, d2 = (t & 31)*2;
        int w0 = (row >> 4)*2, rl = row & 15;
        float m0 = stat[w0*32 + rl*2],     l0 = stat[w0*32 + rl*2 + 1];
        float m1 = stat[(w0+1)*32 + rl*2], l1 = stat[(w0+1)*32 + rl*2 + 1];
        float mm = fmaxf(m0, m1);
        float a0 = __expf(m0 - mm), a1 = __expf(m1 - mm);
        float inv = 1.f / (a0*l0 + a1*l1);
        float o0 = (a0*Osm[(w0*16 + rl)*OSM_STRIDE + d2] +
                    a1*Osm[((w0+1)*16 + rl)*OSM_STRIDE + d2]) * inv;
        float o1 = (a0*Osm[(w0*16 + rl)*OSM_STRIDE + d2 + 1] +
                    a1*Osm[((w0+1)*16 + rl)*OSM_STRIDE + d2 + 1]) * inv;
        size_t gi = (size_t)(b*Nn + i0 + row)*CS + h*HD + d2;
        float2 gg = *(const float2*)(d_g + gi);
        uint32_t hh, ll;
        split2h(gg.x * o0, gg.y * o1, hh, ll);
        *(uint32_t*)((char*)d_goh + gi*2) = hh;
        *(uint32_t*)((char*)d_gol + gi*2) = ll;
    }
}

// ---------------- launch: single stream; bias+proj fused for true overlap ----------------
extern "C" void kernel_launch(void* const* d_in, const int* in_sizes, int n_in,
                              void* d_out, int out_size)
{
    const float* s    = (const float*)d_in[0];
    const float* z    = (const float*)d_in[1];
    const float* mask = (const float*)d_in[2];
    const float* k_in = (const float*)d_in[3];
    const float* Wq   = (const float*)d_in[4];
    const float* bq   = (const float*)d_in[5];
    const float* Wk   = (const float*)d_in[6];
    const float* Wv   = (const float*)d_in[7];
    const float* Wg   = (const float*)d_in[8];
    const float* ln_g = (const float*)d_in[9];
    const float* ln_b = (const float*)d_in[10];
    const float* Wz   = (const float*)d_in[11];
    const float* Wo   = (const float*)d_in[12];
    float* out = (float*)d_out;

    static bool init = false;
    if (!init) {
        init = true;
        cudaFuncSetAttribute(fused_mid,  cudaFuncAttributeMaxDynamicSharedMemorySize, GEMM_SMEM);
        cudaFuncSetAttribute(final_gemm, cudaFuncAttributeMaxDynamicSharedMemorySize, GEMM_SMEM);
        cudaFuncSetAttribute(attn_mma,   cudaFuncAttributeMaxDynamicSharedMemorySize, ATT_SMEM);
    }

    wconv_kernel<<<dim3(WSZ/1024, 5), 256>>>(Wq, Wk, Wv, Wg, Wo);
    aconv_kernel<<<dim3(MROWS*CS/1024, 2), 256>>>(s, k_in);
    prep_kernel<<<1, 128>>>(ln_g, ln_b, Wz);

    fused_mid<<<9984, 256, GEMM_SMEM>>>(bq, z);

    attn_mma<<<dim3(Nn/32, NH, Bn), 128, ATT_SMEM>>>(mask);
    final_gemm<<<dim3(CS/64, MROWS/128), 256, GEMM_SMEM>>>(out);
}

// round 16
// speedup vs baseline: 1.1728x; 1.1728x over previous
#include <cuda_runtime.h>
#include <cuda_bf16.h>
#include <cuda_fp16.h>
#include <cstdint>
#include <cstddef>

#define Bn 2
#define Nn 768
#define CS 1024
#define CZ 128
#define NH 16
#define HD 64
#define MROWS (Bn*Nn)     // 1536
#define NPAIR (Bn*Nn*Nn)  // 1179648
#define WSZ (CS*CS)

// ---------------- scratch (device globals; no allocations allowed) ----------------
__device__ __nv_bfloat16 d_Wh[5*WSZ];                        // weights, single fp16
__device__ __nv_bfloat16 d_inh[2*MROWS*CS], d_inl[2*MROWS*CS]; // s, k_in fp16 2-term
__device__ __nv_bfloat16 d_qh[MROWS*CS], d_ql[MROWS*CS];    // q fp16 2-term
__device__ __nv_bfloat16 d_kh[MROWS*CS];                    // k fp16
__device__ __nv_bfloat16 d_vh[MROWS*CS];                    // v fp16
__device__ __nv_bfloat16 d_goh[MROWS*CS], d_gol[MROWS*CS];  // go fp16 2-term
__device__ float d_g[MROWS*CS];
__device__ __half d_bias[Bn*NH*Nn*Nn];    // fp16 bias (37.7 MB)
__device__ float d_Gz[CZ*NH];
__device__ float d_Bh[NH];
__device__ float d_GzSum[NH];

// ================= helpers ====================
__device__ __forceinline__ void ldsm4(uint32_t* r, uint32_t a) {
    asm volatile("ldmatrix.sync.aligned.m8n8.x4.shared.b16 {%0,%1,%2,%3}, [%4];"
                 : "=r"(r[0]), "=r"(r[1]), "=r"(r[2]), "=r"(r[3]) : "r"(a));
}
__device__ __forceinline__ void ldsm4t(uint32_t* r, uint32_t a) {
    asm volatile("ldmatrix.sync.aligned.m8n8.x4.trans.shared.b16 {%0,%1,%2,%3}, [%4];"
                 : "=r"(r[0]), "=r"(r[1]), "=r"(r[2]), "=r"(r[3]) : "r"(a));
}
__device__ __forceinline__ void mma_bf16(float* c, const uint32_t* a, const uint32_t* b) {
    asm volatile("mma.sync.aligned.m16n8k16.row.col.f32.bf16.bf16.f32 "
                 "{%0,%1,%2,%3}, {%4,%5,%6,%7}, {%8,%9}, {%0,%1,%2,%3};"
                 : "+f"(c[0]), "+f"(c[1]), "+f"(c[2]), "+f"(c[3])
                 : "r"(a[0]), "r"(a[1]), "r"(a[2]), "r"(a[3]), "r"(b[0]), "r"(b[1]));
}
__device__ __forceinline__ void mma_f16(float* c, const uint32_t* a, const uint32_t* b) {
    asm volatile("mma.sync.aligned.m16n8k16.row.col.f32.f16.f16.f32 "
                 "{%0,%1,%2,%3}, {%4,%5,%6,%7}, {%8,%9}, {%0,%1,%2,%3};"
                 : "+f"(c[0]), "+f"(c[1]), "+f"(c[2]), "+f"(c[3])
                 : "r"(a[0]), "r"(a[1]), "r"(a[2]), "r"(a[3]), "r"(b[0]), "r"(b[1]));
}
__device__ __forceinline__ void split2(float x, float y, uint32_t& hi, uint32_t& lo) {
    __nv_bfloat162 h = __float22bfloat162_rn(make_float2(x, y));
    float2 hf = __bfloat1622float2(h);
    __nv_bfloat162 l = __float22bfloat162_rn(make_float2(x - hf.x, y - hf.y));
    hi = *(uint32_t*)&h;
    lo = *(uint32_t*)&l;
}
__device__ __forceinline__ void split2h(float x, float y, uint32_t& hi, uint32_t& lo) {
    __half2 h = __floats2half2_rn(x, y);
    float2 hf = __half22float2(h);
    __half2 l = __floats2half2_rn(x - hf.x, y - hf.y);
    hi = *(uint32_t*)&h;
    lo = *(uint32_t*)&l;
}
#define CPA(dst, src) asm volatile("cp.async.cg.shared.global [%0], [%1], 16;" :: "r"(dst), "l"(src))
#define CPCOMMIT()    asm volatile("cp.async.commit_group;")
#define CPWAIT1()     asm volatile("cp.async.wait_group 1;")

// ---------------- pre-split converters ----------------
__global__ void __launch_bounds__(256) wconv_kernel(
    const float* __restrict__ W0, const float* __restrict__ W1,
    const float* __restrict__ W2, const float* __restrict__ W3,
    const float* __restrict__ W4)
{
    int which = blockIdx.y;
    const float* src = which == 0 ? W0 : which == 1 ? W1 : which == 2 ? W2 :
                       which == 3 ? W3 : W4;
    size_t idx = ((size_t)blockIdx.x * 256 + threadIdx.x) * 4;
    float4 v = *(const float4*)(src + idx);
    __half2 a = __floats2half2_rn(v.x, v.y);
    __half2 b = __floats2half2_rn(v.z, v.w);
    size_t o = (size_t)which * WSZ + idx;
    *(uint2*)((char*)d_Wh + o*2) = make_uint2(*(uint32_t*)&a, *(uint32_t*)&b);
}
__global__ void __launch_bounds__(256) aconv_kernel(
    const float* __restrict__ A0, const float* __restrict__ A1)
{
    int which = blockIdx.y;
    const float* src = which == 0 ? A0 : A1;
    size_t idx = ((size_t)blockIdx.x * 256 + threadIdx.x) * 4;
    float4 v = *(const float4*)(src + idx);
    uint32_t h0, l0, h1, l1;
    split2h(v.x, v.y, h0, l0);
    split2h(v.z, v.w, h1, l1);
    size_t o = (size_t)which * MROWS * CS + idx;
    *(uint2*)((char*)d_inh + o*2) = make_uint2(h0, h1);
    *(uint2*)((char*)d_inl + o*2) = make_uint2(l0, l1);
}

// ================= GEMM: fp16 A (2-term only for q/final), fp16 B, 3-stage =====
#define ASTRIDE 40
#define BSTRIDE 72
#define AHI_OFF 0
#define ALO_OFF 10240
#define BHI_OFF 20480
#define BUFBYTES 25088
#define GEMM_SMEM (3*BUFBYTES)   // 75264

__device__ __forceinline__ void gemm_core(
    const __nv_bfloat16* __restrict__ Ah, const __nv_bfloat16* __restrict__ Al,
    const __nv_bfloat16* __restrict__ Bh,
    const float* __restrict__ bq, int mode,
    float* __restrict__ Cf, __nv_bfloat16* __restrict__ Ch, __nv_bfloat16* __restrict__ Cl)
{
    extern __shared__ char sm_raw[];
    uint32_t sbase = (uint32_t)__cvta_generic_to_shared(sm_raw);
    // 2-term A only where output precision demands it: q (mode 0) and final (mode 4).
    // k/v outputs are truncated to single fp16 anyway; g goes through sigmoid.
    const bool twoterm = (mode == 0 || mode == 4);

    int tid = threadIdx.x;
    int wid = tid >> 5, lane = tid & 31;
    int warpM = wid >> 1, warpN = wid & 1;
    int m0 = blockIdx.y * 128, n0 = blockIdx.x * 64;

    float acc[2][4][4];
    #pragma unroll
    for (int mt = 0; mt < 2; mt++)
        #pragma unroll
        for (int nt = 0; nt < 4; nt++)
            #pragma unroll
            for (int i = 0; i < 4; i++) acc[mt][nt][i] = 0.f;

    int matr = lane >> 3, rr = lane & 7;
    int aRowBase = warpM * 32 + (matr & 1) * 8 + rr;
    int aColBase = (matr >> 1) * 8;
    int bRowBase = (matr & 1) * 8 + rr;
    int bColBase = warpN * 32 + (matr >> 1) * 8;

    int arow = tid >> 2, aq = tid & 3;
    int brow = tid >> 3, bqc = tid & 7;

    auto issue = [&](int c, int buf) {
        uint32_t st = sbase + buf * BUFBYTES;
        #pragma unroll
        for (int r = 0; r < 2; r++) {
            int row = arow + r * 64;
            const __nv_bfloat16* sh = Ah + (size_t)(m0 + row) * CS + c * 32 + aq * 8;
            uint32_t d = st + row * 80 + aq * 16;
            CPA(d + AHI_OFF, sh);
            if (twoterm) {
                const __nv_bfloat16* sl = Al + (size_t)(m0 + row) * CS + c * 32 + aq * 8;
                CPA(d + ALO_OFF, sl);
            }
        }
        {
            const __nv_bfloat16* sh = Bh + (size_t)(c * 32 + brow) * CS + n0 + bqc * 8;
            CPA(st + BHI_OFF + brow * 144 + bqc * 16, sh);
        }
    };

    issue(0, 0); CPCOMMIT();
    issue(1, 1); CPCOMMIT();

    const int CHUNKS = 32;
    for (int c = 0; c < CHUNKS; c++) {
        CPWAIT1();
        __syncthreads();
        if (c + 2 < CHUNKS) issue(c + 2, (c + 2) % 3);
        CPCOMMIT();

        uint32_t off = sbase + (c % 3) * BUFBYTES;
        #pragma unroll
        for (int ks = 0; ks < 32; ks += 16) {
            uint32_t Ahf[2][4], Alf[2][4], Bhf[2][4];
            #pragma unroll
            for (int mt = 0; mt < 2; mt++)
                ldsm4(Ahf[mt], off + AHI_OFF +
                      (((aRowBase + mt * 16) * ASTRIDE) + aColBase + ks) * 2);
            #pragma unroll
            for (int ntp = 0; ntp < 2; ntp++)
                ldsm4t(Bhf[ntp], off + BHI_OFF +
                       (((bRowBase + ks) * BSTRIDE) + bColBase + ntp * 16) * 2);
            #pragma unroll
            for (int mt = 0; mt < 2; mt++)
                #pragma unroll
                for (int nt = 0; nt < 4; nt++)
                    mma_f16(acc[mt][nt], Ahf[mt], &Bhf[nt >> 1][(nt & 1) * 2]);
            if (twoterm) {
                #pragma unroll
                for (int mt = 0; mt < 2; mt++)
                    ldsm4(Alf[mt], off + ALO_OFF +
                          (((aRowBase + mt * 16) * ASTRIDE) + aColBase + ks) * 2);
                #pragma unroll
                for (int mt = 0; mt < 2; mt++)
                    #pragma unroll
                    for (int nt = 0; nt < 4; nt++)
                        mma_f16(acc[mt][nt], Alf[mt], &Bhf[nt >> 1][(nt & 1) * 2]);
            }
        }
    }

    int grp = lane >> 2, tL = lane & 3;
    #pragma unroll
    for (int mt = 0; mt < 2; mt++) {
        #pragma unroll
        for (int nt = 0; nt < 4; nt++) {
            int row = m0 + warpM * 32 + mt * 16 + grp;
            int col = n0 + warpN * 32 + nt * 8 + tL * 2;
            float v0 = acc[mt][nt][0], v1 = acc[mt][nt][1];
            float v2 = acc[mt][nt][2], v3 = acc[mt][nt][3];
            if (mode == 0) {
                float b0 = bq[col], b1 = bq[col + 1];
                v0 = (v0 + b0) * 0.125f; v1 = (v1 + b1) * 0.125f;
                v2 = (v2 + b0) * 0.125f; v3 = (v3 + b1) * 0.125f;
                uint32_t h0, l0, h1, l1;
                split2h(v0, v1, h0, l0);
                split2h(v2, v3, h1, l1);
                *(uint32_t*)((char*)Ch + ((size_t)row * CS + col) * 2)       = h0;
                *(uint32_t*)((char*)Cl + ((size_t)row * CS + col) * 2)       = l0;
                *(uint32_t*)((char*)Ch + ((size_t)(row + 8) * CS + col) * 2) = h1;
                *(uint32_t*)((char*)Cl + ((size_t)(row + 8) * CS + col) * 2) = l1;
            } else if (mode == 1 || mode == 2) {
                __half2 a = __floats2half2_rn(v0, v1);
                __half2 b2 = __floats2half2_rn(v2, v3);
                *(uint32_t*)((char*)Ch + ((size_t)row * CS + col) * 2)       = *(uint32_t*)&a;
                *(uint32_t*)((char*)Ch + ((size_t)(row + 8) * CS + col) * 2) = *(uint32_t*)&b2;
            } else if (mode == 3) {
                v0 = 1.f/(1.f + __expf(-v0)); v1 = 1.f/(1.f + __expf(-v1));
                v2 = 1.f/(1.f + __expf(-v2)); v3 = 1.f/(1.f + __expf(-v3));
                *(float2*)(Cf + (size_t)row * CS + col)       = make_float2(v0, v1);
                *(float2*)(Cf + (size_t)(row + 8) * CS + col) = make_float2(v2, v3);
            } else {
                *(float2*)(Cf + (size_t)row * CS + col)       = make_float2(v0, v1);
                *(float2*)(Cf + (size_t)(row + 8) * CS + col) = make_float2(v2, v3);
            }
        }
    }
}

__global__ void __launch_bounds__(256) proj4_kernel(const float* __restrict__ bq)
{
    int which = blockIdx.z;
    const __nv_bfloat16* Ah = (which == 0 || which == 3) ? d_inh : d_inh + MROWS*CS;
    const __nv_bfloat16* Al = (which == 0 || which == 3) ? d_inl : d_inl + MROWS*CS;
    const __nv_bfloat16* Bh = d_Wh + (size_t)which * WSZ;
    __nv_bfloat16* Ch = which == 0 ? d_qh : which == 1 ? d_kh : which == 2 ? d_vh : nullptr;
    __nv_bfloat16* Cl = which == 0 ? d_ql : nullptr;
    gemm_core(Ah, Al, Bh, bq, which, d_g, Ch, Cl);
}

__global__ void __launch_bounds__(256) final_gemm(float* __restrict__ out)
{
    gemm_core(d_goh, d_gol, d_Wh + 4*(size_t)WSZ, nullptr, 4, out, nullptr, nullptr);
}

// ---------------- fold LN affine into z-projection ----------------
__global__ void prep_kernel(const float* __restrict__ ln_g,
                            const float* __restrict__ ln_b,
                            const float* __restrict__ Wz)
{
    __shared__ float sB[CZ*NH];
    __shared__ float sG[CZ*NH];
    int c = threadIdx.x;
    float g = ln_g[c], bb = ln_b[c];
    #pragma unroll
    for (int h = 0; h < NH; h++) {
        float w = Wz[c*NH + h];
        float gz = g*w;
        d_Gz[c*NH + h] = gz;
        sG[c*NH + h] = gz;
        sB[c*NH + h] = bb*w;
    }
    __syncthreads();
    if (c < NH) {
        float sb = 0.f, sg = 0.f;
        for (int cc = 0; cc < CZ; cc++) { sb += sB[cc*NH + c]; sg += sG[cc*NH + c]; }
        d_Bh[c] = sb;
        d_GzSum[c] = sg;
    }
}

// ====== bias v4: direct gmem fragments with k-permutation (float4 loads), fp16 out ======
#define BM_GH 0
#define BM_GL 6144
#define BM_SG 12288
#define BIAS_SMEM 21504

__global__ void __launch_bounds__(256) bias_mma(const float* __restrict__ z)
{
    extern __shared__ char smraw[];
    uint32_t sb = (uint32_t)__cvta_generic_to_shared(smraw);
    int tid = threadIdx.x, lane = tid & 31, wid = tid >> 5;
    int grp = lane >> 2, tL = lane & 3;
    int t8 = lane >> 3, r8 = lane & 7;

    for (int t = tid; t < CZ*NH; t += 256) {
        int c = t >> 4, hh = t & 15;
        int cb = c & 15, tq = cb >> 2, j = cb & 3;
        int lr = (j < 2) ? (2*tq + j) : (8 + 2*tq + (j - 2));
        int row = (c & 0x70) | lr;
        float w = d_Gz[t];
        __nv_bfloat16 hi = __float2bfloat16(w);
        __nv_bfloat16 lo = __float2bfloat16(w - __bfloat162float(hi));
        ((__nv_bfloat16*)(smraw + BM_GH))[row*24 + hh] = hi;
        ((__nv_bfloat16*)(smraw + BM_GL))[row*24 + hh] = lo;
    }
    __syncthreads();

    const float* z0 = z + (size_t)(blockIdx.x*128 + wid*16 + grp)*CZ;
    const float* z1 = z0 + 8*CZ;

    int gRow = (t8 & 1)*8 + r8;
    int gCol = (t8 >> 1)*8;

    float acc0[4] = {0.f,0.f,0.f,0.f}, acc1[4] = {0.f,0.f,0.f,0.f};
    float s1_0 = 0.f, s2_0 = 0.f, s1_1 = 0.f, s2_1 = 0.f;

    #pragma unroll
    for (int kc = 0; kc < 8; kc++) {
        float4 f = *(const float4*)(z0 + kc*16 + tL*4);
        float4 g = *(const float4*)(z1 + kc*16 + tL*4);

        s1_0 += (f.x + f.y) + (f.z + f.w);
        s2_0 = fmaf(f.x,f.x, fmaf(f.y,f.y, fmaf(f.z,f.z, fmaf(f.w,f.w, s2_0))));
        s1_1 += (g.x + g.y) + (g.z + g.w);
        s2_1 = fmaf(g.x,g.x, fmaf(g.y,g.y, fmaf(g.z,g.z, fmaf(g.w,g.w, s2_1))));

        uint32_t Ahf[4], Alf[4];
        split2(f.x, f.y, Ahf[0], Alf[0]);
        split2(g.x, g.y, Ahf[1], Alf[1]);
        split2(f.z, f.w, Ahf[2], Alf[2]);
        split2(g.z, g.w, Ahf[3], Alf[3]);

        uint32_t Gh[4], Gl[4];
        uint32_t goff = (uint32_t)(((gRow + kc*16)*24 + gCol) * 2);
        ldsm4t(Gh, sb + BM_GH + goff);
        ldsm4t(Gl, sb + BM_GL + goff);

        mma_bf16(acc0, Ahf, &Gh[0]); mma_bf16(acc1, Ahf, &Gh[2]);
        mma_bf16(acc0, Alf, &Gh[0]); mma_bf16(acc1, Alf, &Gh[2]);
        mma_bf16(acc0, Ahf, &Gl[0]); mma_bf16(acc1, Ahf, &Gl[2]);
    }

    s1_0 += __shfl_xor_sync(0xFFFFFFFFu, s1_0, 1);
    s1_0 += __shfl_xor_sync(0xFFFFFFFFu, s1_0, 2);
    s2_0 += __shfl_xor_sync(0xFFFFFFFFu, s2_0, 1);
    s2_0 += __shfl_xor_sync(0xFFFFFFFFu, s2_0, 2);
    s1_1 += __shfl_xor_sync(0xFFFFFFFFu, s1_1, 1);
    s1_1 += __shfl_xor_sync(0xFFFFFFFFu, s1_1, 2);
    s2_1 += __shfl_xor_sync(0xFFFFFFFFu, s2_1, 1);
    s2_1 += __shfl_xor_sync(0xFFFFFFFFu, s2_1, 2);
    float mu0 = s1_0 * (1.f/128.f);
    float rstd0 = rsqrtf(s2_0 * (1.f/128.f) - mu0*mu0 + 1e-5f);
    float mu1 = s1_1 * (1.f/128.f);
    float rstd1 = rsqrtf(s2_1 * (1.f/128.f) - mu1*mu1 + 1e-5f);

    {
        int r0 = wid*16 + grp, r1 = r0 + 8;
        float* stage = (float*)(smraw + BM_SG);
        #pragma unroll
        for (int n = 0; n < 2; n++) {
            float* a = n ? acc1 : acc0;
            int h = n*8 + tL*2;
            float gs0 = d_GzSum[h], gs1 = d_GzSum[h+1];
            float bh0 = d_Bh[h],    bh1 = d_Bh[h+1];
            stage[r0*17 + h]     = rstd0*(a[0] - mu0*gs0) + bh0;
            stage[r0*17 + h + 1] = rstd0*(a[1] - mu0*gs1) + bh1;
            stage[r1*17 + h]     = rstd1*(a[2] - mu1*gs0) + bh0;
            stage[r1*17 + h + 1] = rstd1*(a[3] - mu1*gs1) + bh1;
        }
    }
    __syncthreads();

    {
        int p0  = blockIdx.x * 128;
        int b   = p0 / (Nn*Nn);
        int rem = p0 % (Nn*Nn);
        int ii  = rem / Nn;
        int j0  = rem % Nn;
        float* stage = (float*)(smraw + BM_SG);
        #pragma unroll
        for (int t = tid; t < 128*8; t += 256) {
            int h = t >> 6, rr2 = (t & 63) * 2;
            __half2 val = __floats2half2_rn(stage[rr2*17 + h], stage[(rr2+1)*17 + h]);
            *(__half2*)(d_bias + ((size_t)(b*NH + h)*Nn + ii)*Nn + j0 + rr2) = val;
        }
    }
}

// ========== flash attention: 128 threads, 32-row i-tile ==========
#define AT_STRIDE 72
#define AQ_H 0
#define AQ_L 4608
#define KV0 9216
#define KVSTAGE 18432
#define OSM_OFF 0
#define OSM_STRIDE 68
#define STAT_OFF 17408
#define ATT_SMEM 46080

__global__ void __launch_bounds__(128, 4) attn_mma(const float* __restrict__ mask)
{
    extern __shared__ char smraw[];
    uint32_t sb = (uint32_t)__cvta_generic_to_shared(smraw);
    int tid = threadIdx.x, lane = tid & 31, wid = tid >> 5;
    int warpM = wid >> 1, warpN = wid & 1;
    int b = blockIdx.z, h = blockIdx.y, i0 = blockIdx.x * 32;
    int grp = lane >> 2, tL = lane & 3;
    int t8 = lane >> 3, r8 = lane & 7;

    {
        #pragma unroll
        for (int i = 0; i < 4; i++) {
            int g = tid + i*128;
            int mtx = g >> 8, r = (g >> 3) & 31, q = g & 7;
            const __nv_bfloat16* src = (mtx ? d_ql : d_qh) +
                (size_t)(b*Nn + i0 + r)*CS + h*HD + q*8;
            CPA(sb + mtx*4608 + r*144 + q*16, src);
        }
        #pragma unroll
        for (int i = 0; i < 8; i++) {
            int g = tid + i*128;
            int mtx = g >> 9, r = (g >> 3) & 63, q = g & 7;
            const __nv_bfloat16* src = (mtx ? d_vh : d_kh) +
                (size_t)(b*Nn + r)*CS + h*HD + q*8;
            CPA(sb + KV0 + mtx*9216 + r*144 + q*16, src);
        }
        CPCOMMIT();
    }

    float Oa[8][4];
    #pragma unroll
    for (int t = 0; t < 8; t++) { Oa[t][0]=0.f; Oa[t][1]=0.f; Oa[t][2]=0.f; Oa[t][3]=0.f; }
    float mrow0 = -1e30f, mrow1 = -1e30f, lsum0 = 0.f, lsum1 = 0.f;

    const float* maskp = mask + b*Nn;
    const __half* biasbase = d_bias + ((size_t)(b*NH + h)*Nn + (i0 + warpM*16 + grp))*Nn;

    int aRow  = warpM*16 + (t8 & 1)*8 + r8;
    int aCol  = (t8 >> 1)*8;
    int kRowB = warpN*32 + (t8 >> 1)*8 + r8;
    int kColB = (t8 & 1)*8;
    int vRowB = (t8 & 1)*8 + r8;
    int vColB = (t8 >> 1)*8;

    #pragma unroll 1
    for (int jt = 0; jt < 12; jt++) {
        int j0c = jt * 64;
        __syncthreads();
        if (jt + 1 < 12) {
            int st1 = (jt + 1) & 1;
            #pragma unroll
            for (int i = 0; i < 8; i++) {
                int g = tid + i*128;
                int mtx = g >> 9, r = (g >> 3) & 63, q = g & 7;
                const __nv_bfloat16* src = (mtx ? d_vh : d_kh) +
                    (size_t)(b*Nn + j0c + 64 + r)*CS + h*HD + q*8;
                CPA(sb + KV0 + st1*KVSTAGE + mtx*9216 + r*144 + q*16, src);
            }
        }
        CPCOMMIT();
        CPWAIT1();
        __syncthreads();

        uint32_t ks = sb + KV0 + (jt & 1)*KVSTAGE;

        float S[4][4];
        #pragma unroll
        for (int nt = 0; nt < 4; nt++) { S[nt][0]=0.f; S[nt][1]=0.f; S[nt][2]=0.f; S[nt][3]=0.f; }
        #pragma unroll
        for (int kk = 0; kk < 4; kk++) {
            uint32_t qh_[4], ql_[4], khf[2][4];
            uint32_t aoff = (uint32_t)((aRow*AT_STRIDE + kk*16 + aCol) * 2);
            ldsm4(qh_, sb + AQ_H + aoff);
            ldsm4(ql_, sb + AQ_L + aoff);
            uint32_t koff0 = (uint32_t)((kRowB*AT_STRIDE + kk*16 + kColB) * 2);
            uint32_t koff1 = (uint32_t)(((kRowB+16)*AT_STRIDE + kk*16 + kColB) * 2);
            ldsm4(khf[0], ks + koff0);
            ldsm4(khf[1], ks + koff1);
            #pragma unroll
            for (int nt = 0; nt < 4; nt++)
                mma_f16(S[nt], qh_, &khf[nt >> 1][(nt & 1)*2]);
            #pragma unroll
            for (int nt = 0; nt < 4; nt++)
                mma_f16(S[nt], ql_, &khf[nt >> 1][(nt & 1)*2]);
        }

        #pragma unroll
        for (int nt = 0; nt < 4; nt++) {
            int jc = j0c + warpN*32 + nt*8 + tL*2;
            float2 b0 = __half22float2(*(const __half2*)(biasbase + jc));
            float2 b1 = __half22float2(*(const __half2*)(biasbase + (size_t)8*Nn + jc));
            float2 mv = *(const float2*)(maskp + jc);
            float mk0 = (1.f - mv.x) * (-1000000.0f);
            float mk1 = (1.f - mv.y) * (-1000000.0f);
            S[nt][0] += b0.x + mk0; S[nt][1] += b0.y + mk1;
            S[nt][2] += b1.x + mk0; S[nt][3] += b1.y + mk1;
        }

        float cm0 = fmaxf(fmaxf(S[0][0], S[0][1]), fmaxf(S[1][0], S[1][1]));
        cm0 = fmaxf(cm0, fmaxf(fmaxf(S[2][0], S[2][1]), fmaxf(S[3][0], S[3][1])));
        float cm1 = fmaxf(fmaxf(S[0][2], S[0][3]), fmaxf(S[1][2], S[1][3]));
        cm1 = fmaxf(cm1, fmaxf(fmaxf(S[2][2], S[2][3]), fmaxf(S[3][2], S[3][3])));
        cm0 = fmaxf(cm0, __shfl_xor_sync(0xFFFFFFFFu, cm0, 1));
        cm0 = fmaxf(cm0, __shfl_xor_sync(0xFFFFFFFFu, cm0, 2));
        cm1 = fmaxf(cm1, __shfl_xor_sync(0xFFFFFFFFu, cm1, 1));
        cm1 = fmaxf(cm1, __shfl_xor_sync(0xFFFFFFFFu, cm1, 2));
        float mn0 = fmaxf(mrow0, cm0), mn1 = fmaxf(mrow1, cm1);
        float sc0 = __expf(mrow0 - mn0), sc1 = __expf(mrow1 - mn1);
        mrow0 = mn0; mrow1 = mn1;
        float rs0 = 0.f, rs1 = 0.f;
        #pragma unroll
        for (int nt = 0; nt < 4; nt++) {
            S[nt][0] = __expf(S[nt][0] - mn0);
            S[nt][1] = __expf(S[nt][1] - mn0);
            S[nt][2] = __expf(S[nt][2] - mn1);
            S[nt][3] = __expf(S[nt][3] - mn1);
            rs0 += S[nt][0] + S[nt][1];
            rs1 += S[nt][2] + S[nt][3];
        }
        rs0 += __shfl_xor_sync(0xFFFFFFFFu, rs0, 1);
        rs0 += __shfl_xor_sync(0xFFFFFFFFu, rs0, 2);
        rs1 += __shfl_xor_sync(0xFFFFFFFFu, rs1, 1);
        rs1 += __shfl_xor_sync(0xFFFFFFFFu, rs1, 2);
        lsum0 = lsum0*sc0 + rs0;
        lsum1 = lsum1*sc1 + rs1;
        #pragma unroll
        for (int t = 0; t < 8; t++) {
            Oa[t][0] *= sc0; Oa[t][1] *= sc0;
            Oa[t][2] *= sc1; Oa[t][3] *= sc1;
        }

        uint32_t Ph[2][4], Pl[2][4];
        #pragma unroll
        for (int kf = 0; kf < 2; kf++) {
            split2h(S[2*kf][0],   S[2*kf][1],   Ph[kf][0], Pl[kf][0]);
            split2h(S[2*kf][2],   S[2*kf][3],   Ph[kf][1], Pl[kf][1]);
            split2h(S[2*kf+1][0], S[2*kf+1][1], Ph[kf][2], Pl[kf][2]);
            split2h(S[2*kf+1][2], S[2*kf+1][3], Ph[kf][3], Pl[kf][3]);
        }

        #pragma unroll
        for (int kf = 0; kf < 2; kf++) {
            int kb = warpN*32 + kf*16;
            #pragma unroll
            for (int ntp = 0; ntp < 4; ntp++) {
                uint32_t vhf[4];
                uint32_t voff = (uint32_t)(((kb + vRowB)*AT_STRIDE + ntp*16 + vColB) * 2);
                ldsm4t(vhf, ks + 9216 + voff);
                mma_f16(Oa[ntp*2],   Ph[kf], &vhf[0]);
                mma_f16(Oa[ntp*2+1], Ph[kf], &vhf[2]);
                mma_f16(Oa[ntp*2],   Pl[kf], &vhf[0]);
                mma_f16(Oa[ntp*2+1], Pl[kf], &vhf[2]);
            }
        }
    }

    __syncthreads();
    float* Osm  = (float*)(smraw + OSM_OFF);
    float* stat = (float*)(smraw + STAT_OFF);
    #pragma unroll
    for (int t = 0; t < 8; t++) {
        int dcol = t*8 + tL*2;
        Osm[(wid*16 + grp)*OSM_STRIDE + dcol]       = Oa[t][0];
        Osm[(wid*16 + grp)*OSM_STRIDE + dcol + 1]   = Oa[t][1];
        Osm[(wid*16 + grp+8)*OSM_STRIDE + dcol]     = Oa[t][2];
        Osm[(wid*16 + grp+8)*OSM_STRIDE + dcol + 1] = Oa[t][3];
    }
    if (tL == 0) {
        stat[wid*32 + grp*2]       = mrow0;
        stat[wid*32 + grp*2 + 1]   = lsum0;
        stat[wid*32 + (grp+8)*2]     = mrow1;
        stat[wid*32 + (grp+8)*2 + 1] = lsum1;
    }
    __syncthreads();

    for (int t = tid; t < 32*32; t += 128) {
        int row = t >> 5, d2 = (t & 31)*2;
        int w0 = (row >> 4)*2, rl = row & 15;
        float m0 = stat[w0*32 + rl*2],     l0 = stat[w0*32 + rl*2 + 1];
        float m1 = stat[(w0+1)*32 + rl*2], l1 = stat[(w0+1)*32 + rl*2 + 1];
        float mm = fmaxf(m0, m1);
        float a0 = __expf(m0 - mm), a1 = __expf(m1 - mm);
        float inv = 1.f / (a0*l0 + a1*l1);
        float o0 = (a0*Osm[(w0*16 + rl)*OSM_STRIDE + d2] +
                    a1*Osm[((w0+1)*16 + rl)*OSM_STRIDE + d2]) * inv;
        float o1 = (a0*Osm[(w0*16 + rl)*OSM_STRIDE + d2 + 1] +
                    a1*Osm[((w0+1)*16 + rl)*OSM_STRIDE + d2 + 1]) * inv;
        size_t gi = (size_t)(b*Nn + i0 + row)*CS + h*HD + d2;
        float2 gg = *(const float2*)(d_g + gi);
        uint32_t hh, ll;
        split2h(gg.x * o0, gg.y * o1, hh, ll);
        *(uint32_t*)((char*)d_goh + gi*2) = hh;
        *(uint32_t*)((char*)d_gol + gi*2) = ll;
    }
}

// ---------------- launch (R14 structure; proj4 is submission #4 for ncu) ----------------
extern "C" void kernel_launch(void* const* d_in, const int* in_sizes, int n_in,
                              void* d_out, int out_size)
{
    const float* s    = (const float*)d_in[0];
    const float* z    = (const float*)d_in[1];
    const float* mask = (const float*)d_in[2];
    const float* k_in = (const float*)d_in[3];
    const float* Wq   = (const float*)d_in[4];
    const float* bq   = (const float*)d_in[5];
    const float* Wk   = (const float*)d_in[6];
    const float* Wv   = (const float*)d_in[7];
    const float* Wg   = (const float*)d_in[8];
    const float* ln_g = (const float*)d_in[9];
    const float* ln_b = (const float*)d_in[10];
    const float* Wz   = (const float*)d_in[11];
    const float* Wo   = (const float*)d_in[12];
    float* out = (float*)d_out;

    static cudaStream_t s1 = nullptr, s2 = nullptr;
    static cudaEvent_t evF = nullptr, evJ1 = nullptr, evJ2 = nullptr;
    if (s1 == nullptr) {
        cudaStreamCreateWithFlags(&s1, cudaStreamNonBlocking);
        cudaStreamCreateWithFlags(&s2, cudaStreamNonBlocking);
        cudaEventCreateWithFlags(&evF,  cudaEventDisableTiming);
        cudaEventCreateWithFlags(&evJ1, cudaEventDisableTiming);
        cudaEventCreateWithFlags(&evJ2, cudaEventDisableTiming);
        cudaFuncSetAttribute(proj4_kernel, cudaFuncAttributeMaxDynamicSharedMemorySize, GEMM_SMEM);
        cudaFuncSetAttribute(final_gemm,   cudaFuncAttributeMaxDynamicSharedMemorySize, GEMM_SMEM);
        cudaFuncSetAttribute(attn_mma,     cudaFuncAttributeMaxDynamicSharedMemorySize, ATT_SMEM);
        cudaFuncSetAttribute(bias_mma,     cudaFuncAttributeMaxDynamicSharedMemorySize, BIAS_SMEM);
    }

    cudaEventRecord(evF, 0);
    cudaStreamWaitEvent(s1, evF, 0);
    cudaStreamWaitEvent(s2, evF, 0);

    // chain A (s1): conversions + projections
    wconv_kernel<<<dim3(WSZ/1024, 5), 256, 0, s1>>>(Wq, Wk, Wv, Wg, Wo);
    aconv_kernel<<<dim3(MROWS*CS/1024, 2), 256, 0, s1>>>(s, k_in);

    // chain B (s2): prep + bias
    prep_kernel<<<1, 128, 0, s2>>>(ln_g, ln_b, Wz);
    proj4_kernel<<<dim3(CS/64, MROWS/128, 4), 256, GEMM_SMEM, s1>>>(bq);
    bias_mma<<<NPAIR/128, 256, BIAS_SMEM, s2>>>(z);

    cudaEventRecord(evJ1, s1);
    cudaEventRecord(evJ2, s2);

    // join on the capture stream, then attention + output projection
    cudaStreamWaitEvent(0, evJ1, 0);
    cudaStreamWaitEvent(0, evJ2, 0);
    attn_mma<<<dim3(Nn/32, NH, Bn), 128, ATT_SMEM>>>(mask);
    final_gemm<<<dim3(CS/64, MROWS/128), 256, GEMM_SMEM>>>(out);
}

// round 17
// speedup vs baseline: 1.2540x; 1.0692x over previous
#include <cuda_runtime.h>
#include <cuda_bf16.h>
#include <cuda_fp16.h>
#include <cstdint>
#include <cstddef>

#define Bn 2
#define Nn 768
#define CS 1024
#define CZ 128
#define NH 16
#define HD 64
#define MROWS (Bn*Nn)     // 1536
#define NPAIR (Bn*Nn*Nn)  // 1179648
#define WSZ (CS*CS)

// ---------------- scratch (device globals; no allocations allowed) ----------------
__device__ __nv_bfloat16 d_Wh[5*WSZ];                        // weights, single fp16
__device__ __nv_bfloat16 d_inh[2*MROWS*CS], d_inl[2*MROWS*CS]; // s, k_in fp16 2-term
__device__ __nv_bfloat16 d_qh[MROWS*CS], d_ql[MROWS*CS];    // q fp16 2-term
__device__ __nv_bfloat16 d_kh[MROWS*CS];                    // k fp16
__device__ __nv_bfloat16 d_vh[MROWS*CS];                    // v fp16
__device__ __nv_bfloat16 d_goh[MROWS*CS];                   // go fp16 single
__device__ float d_g[MROWS*CS];
__device__ __half d_bias[Bn*NH*Nn*Nn];    // fp16 bias (37.7 MB)
__device__ float d_Gz[CZ*NH];
__device__ float d_Bh[NH];
__device__ float d_GzSum[NH];

// ================= helpers ====================
__device__ __forceinline__ void ldsm4(uint32_t* r, uint32_t a) {
    asm volatile("ldmatrix.sync.aligned.m8n8.x4.shared.b16 {%0,%1,%2,%3}, [%4];"
                 : "=r"(r[0]), "=r"(r[1]), "=r"(r[2]), "=r"(r[3]) : "r"(a));
}
__device__ __forceinline__ void ldsm4t(uint32_t* r, uint32_t a) {
    asm volatile("ldmatrix.sync.aligned.m8n8.x4.trans.shared.b16 {%0,%1,%2,%3}, [%4];"
                 : "=r"(r[0]), "=r"(r[1]), "=r"(r[2]), "=r"(r[3]) : "r"(a));
}
__device__ __forceinline__ void mma_bf16(float* c, const uint32_t* a, const uint32_t* b) {
    asm volatile("mma.sync.aligned.m16n8k16.row.col.f32.bf16.bf16.f32 "
                 "{%0,%1,%2,%3}, {%4,%5,%6,%7}, {%8,%9}, {%0,%1,%2,%3};"
                 : "+f"(c[0]), "+f"(c[1]), "+f"(c[2]), "+f"(c[3])
                 : "r"(a[0]), "r"(a[1]), "r"(a[2]), "r"(a[3]), "r"(b[0]), "r"(b[1]));
}
__device__ __forceinline__ void mma_f16(float* c, const uint32_t* a, const uint32_t* b) {
    asm volatile("mma.sync.aligned.m16n8k16.row.col.f32.f16.f16.f32 "
                 "{%0,%1,%2,%3}, {%4,%5,%6,%7}, {%8,%9}, {%0,%1,%2,%3};"
                 : "+f"(c[0]), "+f"(c[1]), "+f"(c[2]), "+f"(c[3])
                 : "r"(a[0]), "r"(a[1]), "r"(a[2]), "r"(a[3]), "r"(b[0]), "r"(b[1]));
}
__device__ __forceinline__ void split2(float x, float y, uint32_t& hi, uint32_t& lo) {
    __nv_bfloat162 h = __float22bfloat162_rn(make_float2(x, y));
    float2 hf = __bfloat1622float2(h);
    __nv_bfloat162 l = __float22bfloat162_rn(make_float2(x - hf.x, y - hf.y));
    hi = *(uint32_t*)&h;
    lo = *(uint32_t*)&l;
}
__device__ __forceinline__ void split2h(float x, float y, uint32_t& hi, uint32_t& lo) {
    __half2 h = __floats2half2_rn(x, y);
    float2 hf = __half22float2(h);
    __half2 l = __floats2half2_rn(x - hf.x, y - hf.y);
    hi = *(uint32_t*)&h;
    lo = *(uint32_t*)&l;
}
#define CPA(dst, src) asm volatile("cp.async.cg.shared.global [%0], [%1], 16;" :: "r"(dst), "l"(src))
#define CPCOMMIT()    asm volatile("cp.async.commit_group;")
#define CPWAIT1()     asm volatile("cp.async.wait_group 1;")

// ---------------- pre-split converters ----------------
__global__ void __launch_bounds__(256) wconv_kernel(
    const float* __restrict__ W0, const float* __restrict__ W1,
    const float* __restrict__ W2, const float* __restrict__ W3,
    const float* __restrict__ W4)
{
    int which = blockIdx.y;
    const float* src = which == 0 ? W0 : which == 1 ? W1 : which == 2 ? W2 :
                       which == 3 ? W3 : W4;
    size_t idx = ((size_t)blockIdx.x * 256 + threadIdx.x) * 4;
    float4 v = *(const float4*)(src + idx);
    __half2 a = __floats2half2_rn(v.x, v.y);
    __half2 b = __floats2half2_rn(v.z, v.w);
    size_t o = (size_t)which * WSZ + idx;
    *(uint2*)((char*)d_Wh + o*2) = make_uint2(*(uint32_t*)&a, *(uint32_t*)&b);
}
__global__ void __launch_bounds__(256) aconv_kernel(
    const float* __restrict__ A0, const float* __restrict__ A1)
{
    int which = blockIdx.y;
    const float* src = which == 0 ? A0 : A1;
    size_t idx = ((size_t)blockIdx.x * 256 + threadIdx.x) * 4;
    float4 v = *(const float4*)(src + idx);
    uint32_t h0, l0, h1, l1;
    split2h(v.x, v.y, h0, l0);
    split2h(v.z, v.w, h1, l1);
    size_t o = (size_t)which * MROWS * CS + idx;
    *(uint2*)((char*)d_inh + o*2) = make_uint2(h0, h1);
    *(uint2*)((char*)d_inl + o*2) = make_uint2(l0, l1);
}

// ================= GEMM: fp16 A (2-term only for q), fp16 B, 3-stage =====
#define ASTRIDE 40
#define BSTRIDE 72
#define AHI_OFF 0
#define ALO_OFF 10240
#define BHI_OFF 20480
#define BUFBYTES 25088
#define GEMM_SMEM (3*BUFBYTES)   // 75264

__device__ __forceinline__ void gemm_core(
    const __nv_bfloat16* __restrict__ Ah, const __nv_bfloat16* __restrict__ Al,
    const __nv_bfloat16* __restrict__ Bh,
    const float* __restrict__ bq, int mode,
    float* __restrict__ Cf, __nv_bfloat16* __restrict__ Ch, __nv_bfloat16* __restrict__ Cl)
{
    extern __shared__ char sm_raw[];
    uint32_t sbase = (uint32_t)__cvta_generic_to_shared(sm_raw);
    // 2-term A only for q (mode 0): k/v truncate to fp16, g passes sigmoid,
    // final (mode 4) tolerates single-fp16 A (output rel err ~2.8e-4, in budget).
    const bool twoterm = (mode == 0);

    int tid = threadIdx.x;
    int wid = tid >> 5, lane = tid & 31;
    int warpM = wid >> 1, warpN = wid & 1;
    int m0 = blockIdx.y * 128, n0 = blockIdx.x * 64;

    float acc[2][4][4];
    #pragma unroll
    for (int mt = 0; mt < 2; mt++)
        #pragma unroll
        for (int nt = 0; nt < 4; nt++)
            #pragma unroll
            for (int i = 0; i < 4; i++) acc[mt][nt][i] = 0.f;

    int matr = lane >> 3, rr = lane & 7;
    int aRowBase = warpM * 32 + (matr & 1) * 8 + rr;
    int aColBase = (matr >> 1) * 8;
    int bRowBase = (matr & 1) * 8 + rr;
    int bColBase = warpN * 32 + (matr >> 1) * 8;

    int arow = tid >> 2, aq = tid & 3;
    int brow = tid >> 3, bqc = tid & 7;

    auto issue = [&](int c, int buf) {
        uint32_t st = sbase + buf * BUFBYTES;
        #pragma unroll
        for (int r = 0; r < 2; r++) {
            int row = arow + r * 64;
            const __nv_bfloat16* sh = Ah + (size_t)(m0 + row) * CS + c * 32 + aq * 8;
            uint32_t d = st + row * 80 + aq * 16;
            CPA(d + AHI_OFF, sh);
            if (twoterm) {
                const __nv_bfloat16* sl = Al + (size_t)(m0 + row) * CS + c * 32 + aq * 8;
                CPA(d + ALO_OFF, sl);
            }
        }
        {
            const __nv_bfloat16* sh = Bh + (size_t)(c * 32 + brow) * CS + n0 + bqc * 8;
            CPA(st + BHI_OFF + brow * 144 + bqc * 16, sh);
        }
    };

    issue(0, 0); CPCOMMIT();
    issue(1, 1); CPCOMMIT();

    const int CHUNKS = 32;
    for (int c = 0; c < CHUNKS; c++) {
        CPWAIT1();
        __syncthreads();
        if (c + 2 < CHUNKS) issue(c + 2, (c + 2) % 3);
        CPCOMMIT();

        uint32_t off = sbase + (c % 3) * BUFBYTES;
        #pragma unroll
        for (int ks = 0; ks < 32; ks += 16) {
            uint32_t Ahf[2][4], Alf[2][4], Bhf[2][4];
            #pragma unroll
            for (int mt = 0; mt < 2; mt++)
                ldsm4(Ahf[mt], off + AHI_OFF +
                      (((aRowBase + mt * 16) * ASTRIDE) + aColBase + ks) * 2);
            #pragma unroll
            for (int ntp = 0; ntp < 2; ntp++)
                ldsm4t(Bhf[ntp], off + BHI_OFF +
                       (((bRowBase + ks) * BSTRIDE) + bColBase + ntp * 16) * 2);
            #pragma unroll
            for (int mt = 0; mt < 2; mt++)
                #pragma unroll
                for (int nt = 0; nt < 4; nt++)
                    mma_f16(acc[mt][nt], Ahf[mt], &Bhf[nt >> 1][(nt & 1) * 2]);
            if (twoterm) {
                #pragma unroll
                for (int mt = 0; mt < 2; mt++)
                    ldsm4(Alf[mt], off + ALO_OFF +
                          (((aRowBase + mt * 16) * ASTRIDE) + aColBase + ks) * 2);
                #pragma unroll
                for (int mt = 0; mt < 2; mt++)
                    #pragma unroll
                    for (int nt = 0; nt < 4; nt++)
                        mma_f16(acc[mt][nt], Alf[mt], &Bhf[nt >> 1][(nt & 1) * 2]);
            }
        }
    }

    int grp = lane >> 2, tL = lane & 3;
    #pragma unroll
    for (int mt = 0; mt < 2; mt++) {
        #pragma unroll
        for (int nt = 0; nt < 4; nt++) {
            int row = m0 + warpM * 32 + mt * 16 + grp;
            int col = n0 + warpN * 32 + nt * 8 + tL * 2;
            float v0 = acc[mt][nt][0], v1 = acc[mt][nt][1];
            float v2 = acc[mt][nt][2], v3 = acc[mt][nt][3];
            if (mode == 0) {
                float b0 = bq[col], b1 = bq[col + 1];
                v0 = (v0 + b0) * 0.125f; v1 = (v1 + b1) * 0.125f;
                v2 = (v2 + b0) * 0.125f; v3 = (v3 + b1) * 0.125f;
                uint32_t h0, l0, h1, l1;
                split2h(v0, v1, h0, l0);
                split2h(v2, v3, h1, l1);
                *(uint32_t*)((char*)Ch + ((size_t)row * CS + col) * 2)       = h0;
                *(uint32_t*)((char*)Cl + ((size_t)row * CS + col) * 2)       = l0;
                *(uint32_t*)((char*)Ch + ((size_t)(row + 8) * CS + col) * 2) = h1;
                *(uint32_t*)((char*)Cl + ((size_t)(row + 8) * CS + col) * 2) = l1;
            } else if (mode == 1 || mode == 2) {
                __half2 a = __floats2half2_rn(v0, v1);
                __half2 b2 = __floats2half2_rn(v2, v3);
                *(uint32_t*)((char*)Ch + ((size_t)row * CS + col) * 2)       = *(uint32_t*)&a;
                *(uint32_t*)((char*)Ch + ((size_t)(row + 8) * CS + col) * 2) = *(uint32_t*)&b2;
            } else if (mode == 3) {
                v0 = 1.f/(1.f + __expf(-v0)); v1 = 1.f/(1.f + __expf(-v1));
                v2 = 1.f/(1.f + __expf(-v2)); v3 = 1.f/(1.f + __expf(-v3));
                *(float2*)(Cf + (size_t)row * CS + col)       = make_float2(v0, v1);
                *(float2*)(Cf + (size_t)(row + 8) * CS + col) = make_float2(v2, v3);
            } else {
                *(float2*)(Cf + (size_t)row * CS + col)       = make_float2(v0, v1);
                *(float2*)(Cf + (size_t)(row + 8) * CS + col) = make_float2(v2, v3);
            }
        }
    }
}

__global__ void __launch_bounds__(256) proj4_kernel(const float* __restrict__ bq)
{
    int which = blockIdx.z;
    const __nv_bfloat16* Ah = (which == 0 || which == 3) ? d_inh : d_inh + MROWS*CS;
    const __nv_bfloat16* Al = (which == 0 || which == 3) ? d_inl : d_inl + MROWS*CS;
    const __nv_bfloat16* Bh = d_Wh + (size_t)which * WSZ;
    __nv_bfloat16* Ch = which == 0 ? d_qh : which == 1 ? d_kh : which == 2 ? d_vh : nullptr;
    __nv_bfloat16* Cl = which == 0 ? d_ql : nullptr;
    gemm_core(Ah, Al, Bh, bq, which, d_g, Ch, Cl);
}

__global__ void __launch_bounds__(256) final_gemm(float* __restrict__ out)
{
    gemm_core(d_goh, nullptr, d_Wh + 4*(size_t)WSZ, nullptr, 4, out, nullptr, nullptr);
}

// ---------------- fold LN affine into z-projection ----------------
__global__ void prep_kernel(const float* __restrict__ ln_g,
                            const float* __restrict__ ln_b,
                            const float* __restrict__ Wz)
{
    __shared__ float sB[CZ*NH];
    __shared__ float sG[CZ*NH];
    int c = threadIdx.x;
    float g = ln_g[c], bb = ln_b[c];
    #pragma unroll
    for (int h = 0; h < NH; h++) {
        float w = Wz[c*NH + h];
        float gz = g*w;
        d_Gz[c*NH + h] = gz;
        sG[c*NH + h] = gz;
        sB[c*NH + h] = bb*w;
    }
    __syncthreads();
    if (c < NH) {
        float sb = 0.f, sg = 0.f;
        for (int cc = 0; cc < CZ; cc++) { sb += sB[cc*NH + c]; sg += sG[cc*NH + c]; }
        d_Bh[c] = sb;
        d_GzSum[c] = sg;
    }
}

// ====== bias v4: direct gmem fragments with k-permutation (float4 loads), fp16 out ======
#define BM_GH 0
#define BM_GL 6144
#define BM_SG 12288
#define BIAS_SMEM 21504

__global__ void __launch_bounds__(256) bias_mma(const float* __restrict__ z)
{
    extern __shared__ char smraw[];
    uint32_t sb = (uint32_t)__cvta_generic_to_shared(smraw);
    int tid = threadIdx.x, lane = tid & 31, wid = tid >> 5;
    int grp = lane >> 2, tL = lane & 3;
    int t8 = lane >> 3, r8 = lane & 7;

    for (int t = tid; t < CZ*NH; t += 256) {
        int c = t >> 4, hh = t & 15;
        int cb = c & 15, tq = cb >> 2, j = cb & 3;
        int lr = (j < 2) ? (2*tq + j) : (8 + 2*tq + (j - 2));
        int row = (c & 0x70) | lr;
        float w = d_Gz[t];
        __nv_bfloat16 hi = __float2bfloat16(w);
        __nv_bfloat16 lo = __float2bfloat16(w - __bfloat162float(hi));
        ((__nv_bfloat16*)(smraw + BM_GH))[row*24 + hh] = hi;
        ((__nv_bfloat16*)(smraw + BM_GL))[row*24 + hh] = lo;
    }
    __syncthreads();

    const float* z0 = z + (size_t)(blockIdx.x*128 + wid*16 + grp)*CZ;
    const float* z1 = z0 + 8*CZ;

    int gRow = (t8 & 1)*8 + r8;
    int gCol = (t8 >> 1)*8;

    float acc0[4] = {0.f,0.f,0.f,0.f}, acc1[4] = {0.f,0.f,0.f,0.f};
    float s1_0 = 0.f, s2_0 = 0.f, s1_1 = 0.f, s2_1 = 0.f;

    #pragma unroll
    for (int kc = 0; kc < 8; kc++) {
        float4 f = *(const float4*)(z0 + kc*16 + tL*4);
        float4 g = *(const float4*)(z1 + kc*16 + tL*4);

        s1_0 += (f.x + f.y) + (f.z + f.w);
        s2_0 = fmaf(f.x,f.x, fmaf(f.y,f.y, fmaf(f.z,f.z, fmaf(f.w,f.w, s2_0))));
        s1_1 += (g.x + g.y) + (g.z + g.w);
        s2_1 = fmaf(g.x,g.x, fmaf(g.y,g.y, fmaf(g.z,g.z, fmaf(g.w,g.w, s2_1))));

        uint32_t Ahf[4], Alf[4];
        split2(f.x, f.y, Ahf[0], Alf[0]);
        split2(g.x, g.y, Ahf[1], Alf[1]);
        split2(f.z, f.w, Ahf[2], Alf[2]);
        split2(g.z, g.w, Ahf[3], Alf[3]);

        uint32_t Gh[4], Gl[4];
        uint32_t goff = (uint32_t)(((gRow + kc*16)*24 + gCol) * 2);
        ldsm4t(Gh, sb + BM_GH + goff);
        ldsm4t(Gl, sb + BM_GL + goff);

        mma_bf16(acc0, Ahf, &Gh[0]); mma_bf16(acc1, Ahf, &Gh[2]);
        mma_bf16(acc0, Alf, &Gh[0]); mma_bf16(acc1, Alf, &Gh[2]);
        mma_bf16(acc0, Ahf, &Gl[0]); mma_bf16(acc1, Ahf, &Gl[2]);
    }

    s1_0 += __shfl_xor_sync(0xFFFFFFFFu, s1_0, 1);
    s1_0 += __shfl_xor_sync(0xFFFFFFFFu, s1_0, 2);
    s2_0 += __shfl_xor_sync(0xFFFFFFFFu, s2_0, 1);
    s2_0 += __shfl_xor_sync(0xFFFFFFFFu, s2_0, 2);
    s1_1 += __shfl_xor_sync(0xFFFFFFFFu, s1_1, 1);
    s1_1 += __shfl_xor_sync(0xFFFFFFFFu, s1_1, 2);
    s2_1 += __shfl_xor_sync(0xFFFFFFFFu, s2_1, 1);
    s2_1 += __shfl_xor_sync(0xFFFFFFFFu, s2_1, 2);
    float mu0 = s1_0 * (1.f/128.f);
    float rstd0 = rsqrtf(s2_0 * (1.f/128.f) - mu0*mu0 + 1e-5f);
    float mu1 = s1_1 * (1.f/128.f);
    float rstd1 = rsqrtf(s2_1 * (1.f/128.f) - mu1*mu1 + 1e-5f);

    {
        int r0 = wid*16 + grp, r1 = r0 + 8;
        float* stage = (float*)(smraw + BM_SG);
        #pragma unroll
        for (int n = 0; n < 2; n++) {
            float* a = n ? acc1 : acc0;
            int h = n*8 + tL*2;
            float gs0 = d_GzSum[h], gs1 = d_GzSum[h+1];
            float bh0 = d_Bh[h],    bh1 = d_Bh[h+1];
            stage[r0*17 + h]     = rstd0*(a[0] - mu0*gs0) + bh0;
            stage[r0*17 + h + 1] = rstd0*(a[1] - mu0*gs1) + bh1;
            stage[r1*17 + h]     = rstd1*(a[2] - mu1*gs0) + bh0;
            stage[r1*17 + h + 1] = rstd1*(a[3] - mu1*gs1) + bh1;
        }
    }
    __syncthreads();

    {
        int p0  = blockIdx.x * 128;
        int b   = p0 / (Nn*Nn);
        int rem = p0 % (Nn*Nn);
        int ii  = rem / Nn;
        int j0  = rem % Nn;
        float* stage = (float*)(smraw + BM_SG);
        #pragma unroll
        for (int t = tid; t < 128*8; t += 256) {
            int h = t >> 6, rr2 = (t & 63) * 2;
            __half2 val = __floats2half2_rn(stage[rr2*17 + h], stage[(rr2+1)*17 + h]);
            *(__half2*)(d_bias + ((size_t)(b*NH + h)*Nn + ii)*Nn + j0 + rr2) = val;
        }
    }
}

// ========== flash attention: 128 threads, 32-row i-tile ==========
#define AT_STRIDE 72
#define AQ_H 0
#define AQ_L 4608
#define KV0 9216
#define KVSTAGE 18432
#define OSM_OFF 0
#define OSM_STRIDE 68
#define STAT_OFF 17408
#define ATT_SMEM 46080

__global__ void __launch_bounds__(128, 4) attn_mma(const float* __restrict__ mask)
{
    extern __shared__ char smraw[];
    uint32_t sb = (uint32_t)__cvta_generic_to_shared(smraw);
    int tid = threadIdx.x, lane = tid & 31, wid = tid >> 5;
    int warpM = wid >> 1, warpN = wid & 1;
    int b = blockIdx.z, h = blockIdx.y, i0 = blockIdx.x * 32;
    int grp = lane >> 2, tL = lane & 3;
    int t8 = lane >> 3, r8 = lane & 7;

    {
        #pragma unroll
        for (int i = 0; i < 4; i++) {
            int g = tid + i*128;
            int mtx = g >> 8, r = (g >> 3) & 31, q = g & 7;
            const __nv_bfloat16* src = (mtx ? d_ql : d_qh) +
                (size_t)(b*Nn + i0 + r)*CS + h*HD + q*8;
            CPA(sb + mtx*4608 + r*144 + q*16, src);
        }
        #pragma unroll
        for (int i = 0; i < 8; i++) {
            int g = tid + i*128;
            int mtx = g >> 9, r = (g >> 3) & 63, q = g & 7;
            const __nv_bfloat16* src = (mtx ? d_vh : d_kh) +
                (size_t)(b*Nn + r)*CS + h*HD + q*8;
            CPA(sb + KV0 + mtx*9216 + r*144 + q*16, src);
        }
        CPCOMMIT();
    }

    float Oa[8][4];
    #pragma unroll
    for (int t = 0; t < 8; t++) { Oa[t][0]=0.f; Oa[t][1]=0.f; Oa[t][2]=0.f; Oa[t][3]=0.f; }
    float mrow0 = -1e30f, mrow1 = -1e30f, lsum0 = 0.f, lsum1 = 0.f;

    const float* maskp = mask + b*Nn;
    const __half* biasbase = d_bias + ((size_t)(b*NH + h)*Nn + (i0 + warpM*16 + grp))*Nn;

    int aRow  = warpM*16 + (t8 & 1)*8 + r8;
    int aCol  = (t8 >> 1)*8;
    int kRowB = warpN*32 + (t8 >> 1)*8 + r8;
    int kColB = (t8 & 1)*8;
    int vRowB = (t8 & 1)*8 + r8;
    int vColB = (t8 >> 1)*8;

    #pragma unroll 1
    for (int jt = 0; jt < 12; jt++) {
        int j0c = jt * 64;
        __syncthreads();
        if (jt + 1 < 12) {
            int st1 = (jt + 1) & 1;
            #pragma unroll
            for (int i = 0; i < 8; i++) {
                int g = tid + i*128;
                int mtx = g >> 9, r = (g >> 3) & 63, q = g & 7;
                const __nv_bfloat16* src = (mtx ? d_vh : d_kh) +
                    (size_t)(b*Nn + j0c + 64 + r)*CS + h*HD + q*8;
                CPA(sb + KV0 + st1*KVSTAGE + mtx*9216 + r*144 + q*16, src);
            }
        }
        CPCOMMIT();
        CPWAIT1();
        __syncthreads();

        uint32_t ks = sb + KV0 + (jt & 1)*KVSTAGE;

        float S[4][4];
        #pragma unroll
        for (int nt = 0; nt < 4; nt++) { S[nt][0]=0.f; S[nt][1]=0.f; S[nt][2]=0.f; S[nt][3]=0.f; }
        #pragma unroll
        for (int kk = 0; kk < 4; kk++) {
            uint32_t qh_[4], ql_[4], khf[2][4];
            uint32_t aoff = (uint32_t)((aRow*AT_STRIDE + kk*16 + aCol) * 2);
            ldsm4(qh_, sb + AQ_H + aoff);
            ldsm4(ql_, sb + AQ_L + aoff);
            uint32_t koff0 = (uint32_t)((kRowB*AT_STRIDE + kk*16 + kColB) * 2);
            uint32_t koff1 = (uint32_t)(((kRowB+16)*AT_STRIDE + kk*16 + kColB) * 2);
            ldsm4(khf[0], ks + koff0);
            ldsm4(khf[1], ks + koff1);
            #pragma unroll
            for (int nt = 0; nt < 4; nt++)
                mma_f16(S[nt], qh_, &khf[nt >> 1][(nt & 1)*2]);
            #pragma unroll
            for (int nt = 0; nt < 4; nt++)
                mma_f16(S[nt], ql_, &khf[nt >> 1][(nt & 1)*2]);
        }

        #pragma unroll
        for (int nt = 0; nt < 4; nt++) {
            int jc = j0c + warpN*32 + nt*8 + tL*2;
            float2 b0 = __half22float2(*(const __half2*)(biasbase + jc));
            float2 b1 = __half22float2(*(const __half2*)(biasbase + (size_t)8*Nn + jc));
            float2 mv = *(const float2*)(maskp + jc);
            float mk0 = (1.f - mv.x) * (-1000000.0f);
            float mk1 = (1.f - mv.y) * (-1000000.0f);
            S[nt][0] += b0.x + mk0; S[nt][1] += b0.y + mk1;
            S[nt][2] += b1.x + mk0; S[nt][3] += b1.y + mk1;
        }

        float cm0 = fmaxf(fmaxf(S[0][0], S[0][1]), fmaxf(S[1][0], S[1][1]));
        cm0 = fmaxf(cm0, fmaxf(fmaxf(S[2][0], S[2][1]), fmaxf(S[3][0], S[3][1])));
        float cm1 = fmaxf(fmaxf(S[0][2], S[0][3]), fmaxf(S[1][2], S[1][3]));
        cm1 = fmaxf(cm1, fmaxf(fmaxf(S[2][2], S[2][3]), fmaxf(S[3][2], S[3][3])));
        cm0 = fmaxf(cm0, __shfl_xor_sync(0xFFFFFFFFu, cm0, 1));
        cm0 = fmaxf(cm0, __shfl_xor_sync(0xFFFFFFFFu, cm0, 2));
        cm1 = fmaxf(cm1, __shfl_xor_sync(0xFFFFFFFFu, cm1, 1));
        cm1 = fmaxf(cm1, __shfl_xor_sync(0xFFFFFFFFu, cm1, 2));
        float mn0 = fmaxf(mrow0, cm0), mn1 = fmaxf(mrow1, cm1);
        float sc0 = __expf(mrow0 - mn0), sc1 = __expf(mrow1 - mn1);
        mrow0 = mn0; mrow1 = mn1;
        float rs0 = 0.f, rs1 = 0.f;
        #pragma unroll
        for (int nt = 0; nt < 4; nt++) {
            S[nt][0] = __expf(S[nt][0] - mn0);
            S[nt][1] = __expf(S[nt][1] - mn0);
            S[nt][2] = __expf(S[nt][2] - mn1);
            S[nt][3] = __expf(S[nt][3] - mn1);
            rs0 += S[nt][0] + S[nt][1];
            rs1 += S[nt][2] + S[nt][3];
        }
        rs0 += __shfl_xor_sync(0xFFFFFFFFu, rs0, 1);
        rs0 += __shfl_xor_sync(0xFFFFFFFFu, rs0, 2);
        rs1 += __shfl_xor_sync(0xFFFFFFFFu, rs1, 1);
        rs1 += __shfl_xor_sync(0xFFFFFFFFu, rs1, 2);
        lsum0 = lsum0*sc0 + rs0;
        lsum1 = lsum1*sc1 + rs1;
        #pragma unroll
        for (int t = 0; t < 8; t++) {
            Oa[t][0] *= sc0; Oa[t][1] *= sc0;
            Oa[t][2] *= sc1; Oa[t][3] *= sc1;
        }

        uint32_t Ph[2][4], Pl[2][4];
        #pragma unroll
        for (int kf = 0; kf < 2; kf++) {
            split2h(S[2*kf][0],   S[2*kf][1],   Ph[kf][0], Pl[kf][0]);
            split2h(S[2*kf][2],   S[2*kf][3],   Ph[kf][1], Pl[kf][1]);
            split2h(S[2*kf+1][0], S[2*kf+1][1], Ph[kf][2], Pl[kf][2]);
            split2h(S[2*kf+1][2], S[2*kf+1][3], Ph[kf][3], Pl[kf][3]);
        }

        #pragma unroll
        for (int kf = 0; kf < 2; kf++) {
            int kb = warpN*32 + kf*16;
            #pragma unroll
            for (int ntp = 0; ntp < 4; ntp++) {
                uint32_t vhf[4];
                uint32_t voff = (uint32_t)(((kb + vRowB)*AT_STRIDE + ntp*16 + vColB) * 2);
                ldsm4t(vhf, ks + 9216 + voff);
                mma_f16(Oa[ntp*2],   Ph[kf], &vhf[0]);
                mma_f16(Oa[ntp*2+1], Ph[kf], &vhf[2]);
                mma_f16(Oa[ntp*2],   Pl[kf], &vhf[0]);
                mma_f16(Oa[ntp*2+1], Pl[kf], &vhf[2]);
            }
        }
    }

    __syncthreads();
    float* Osm  = (float*)(smraw + OSM_OFF);
    float* stat = (float*)(smraw + STAT_OFF);
    #pragma unroll
    for (int t = 0; t < 8; t++) {
        int dcol = t*8 + tL*2;
        Osm[(wid*16 + grp)*OSM_STRIDE + dcol]       = Oa[t][0];
        Osm[(wid*16 + grp)*OSM_STRIDE + dcol + 1]   = Oa[t][1];
        Osm[(wid*16 + grp+8)*OSM_STRIDE + dcol]     = Oa[t][2];
        Osm[(wid*16 + grp+8)*OSM_STRIDE + dcol + 1] = Oa[t][3];
    }
    if (tL == 0) {
        stat[wid*32 + grp*2]       = mrow0;
        stat[wid*32 + grp*2 + 1]   = lsum0;
        stat[wid*32 + (grp+8)*2]     = mrow1;
        stat[wid*32 + (grp+8)*2 + 1] = lsum1;
    }
    __syncthreads();

    for (int t = tid; t < 32*32; t += 128) {
        int row = t >> 5, d2 = (t & 31)*2;
        int w0 = (row >> 4)*2, rl = row & 15;
        float m0 = stat[w0*32 + rl*2],     l0 = stat[w0*32 + rl*2 + 1];
        float m1 = stat[(w0+1)*32 + rl*2], l1 = stat[(w0+1)*32 + rl*2 + 1];
        float mm = fmaxf(m0, m1);
        float a0 = __expf(m0 - mm), a1 = __expf(m1 - mm);
        float inv = 1.f / (a0*l0 + a1*l1);
        float o0 = (a0*Osm[(w0*16 + rl)*OSM_STRIDE + d2] +
                    a1*Osm[((w0+1)*16 + rl)*OSM_STRIDE + d2]) * inv;
        float o1 = (a0*Osm[(w0*16 + rl)*OSM_STRIDE + d2 + 1] +
                    a1*Osm[((w0+1)*16 + rl)*OSM_STRIDE + d2 + 1]) * inv;
        size_t gi = (size_t)(b*Nn + i0 + row)*CS + h*HD + d2;
        float2 gg = *(const float2*)(d_g + gi);
        __half2 hv = __floats2half2_rn(gg.x * o0, gg.y * o1);
        *(uint32_t*)((char*)d_goh + gi*2) = *(uint32_t*)&hv;
    }
}

// ---------------- launch: prioritized streams; proj4 is submission #4 for ncu ----------------
extern "C" void kernel_launch(void* const* d_in, const int* in_sizes, int n_in,
                              void* d_out, int out_size)
{
    const float* s    = (const float*)d_in[0];
    const float* z    = (const float*)d_in[1];
    const float* mask = (const float*)d_in[2];
    const float* k_in = (const float*)d_in[3];
    const float* Wq   = (const float*)d_in[4];
    const float* bq   = (const float*)d_in[5];
    const float* Wk   = (const float*)d_in[6];
    const float* Wv   = (const float*)d_in[7];
    const float* Wg   = (const float*)d_in[8];
    const float* ln_g = (const float*)d_in[9];
    const float* ln_b = (const float*)d_in[10];
    const float* Wz   = (const float*)d_in[11];
    const float* Wo   = (const float*)d_in[12];
    float* out = (float*)d_out;

    static cudaStream_t s1 = nullptr, s2 = nullptr;
    static cudaEvent_t evF = nullptr, evJ1 = nullptr, evJ2 = nullptr;
    if (s1 == nullptr) {
        int lo, hi;
        cudaDeviceGetStreamPriorityRange(&lo, &hi);
        cudaStreamCreateWithPriority(&s1, cudaStreamNonBlocking, hi);  // proj chain: high
        cudaStreamCreateWithPriority(&s2, cudaStreamNonBlocking, lo);  // bias chain: low
        cudaEventCreateWithFlags(&evF,  cudaEventDisableTiming);
        cudaEventCreateWithFlags(&evJ1, cudaEventDisableTiming);
        cudaEventCreateWithFlags(&evJ2, cudaEventDisableTiming);
        cudaFuncSetAttribute(proj4_kernel, cudaFuncAttributeMaxDynamicSharedMemorySize, GEMM_SMEM);
        cudaFuncSetAttribute(final_gemm,   cudaFuncAttributeMaxDynamicSharedMemorySize, GEMM_SMEM);
        cudaFuncSetAttribute(attn_mma,     cudaFuncAttributeMaxDynamicSharedMemorySize, ATT_SMEM);
        cudaFuncSetAttribute(bias_mma,     cudaFuncAttributeMaxDynamicSharedMemorySize, BIAS_SMEM);
    }

    cudaEventRecord(evF, 0);
    cudaStreamWaitEvent(s1, evF, 0);
    cudaStreamWaitEvent(s2, evF, 0);

    // chain A (s1, high prio): conversions + projections
    wconv_kernel<<<dim3(WSZ/1024, 5), 256, 0, s1>>>(Wq, Wk, Wv, Wg, Wo);
    aconv_kernel<<<dim3(MROWS*CS/1024, 2), 256, 0, s1>>>(s, k_in);

    // chain B (s2, low prio): prep + bias
    prep_kernel<<<1, 128, 0, s2>>>(ln_g, ln_b, Wz);
    proj4_kernel<<<dim3(CS/64, MROWS/128, 4), 256, GEMM_SMEM, s1>>>(bq);
    bias_mma<<<NPAIR/128, 256, BIAS_SMEM, s2>>>(z);

    cudaEventRecord(evJ1, s1);
    cudaEventRecord(evJ2, s2);

    // join on the capture stream, then attention + output projection
    cudaStreamWaitEvent(0, evJ1, 0);
    cudaStreamWaitEvent(0, evJ2, 0);
    attn_mma<<<dim3(Nn/32, NH, Bn), 128, ATT_SMEM>>>(mask);
    final_gemm<<<dim3(CS/64, MROWS/128), 256, GEMM_SMEM>>>(out);
}